// round 11
// baseline (speedup 1.0000x reference)
#include <cuda_runtime.h>
#include <cuda_fp16.h>
#include <math.h>
#include <stdint.h>

#define NB 2
#define NS 1024
#define ND 1024
#define NH 16
#define NE 8
#define NF 4096
#define NT 2048

#define TM 128
#define TN 128
#define KC 32
#define A_STRIDE 40    // fp16 elems per A smem row (80B)
#define B_STRIDE 136   // fp16 elems per B smem row (272B)

// 4-stage fp16 pipeline
#define ST_A 0
#define ST_B 10240
#define STAGE_BYTES 18944
#define NST1 4
#define GEMM_SMEM (NST1 * STAGE_BYTES)

#define F_STRIDE 72    // flash smem row stride (144B)
#define F_Q 0
#define F_KV0 9216     // K buf0 @9216, V buf0 @18432, K buf1 @27648, V buf1 @36864
#define FLASH_SMEM 46080

#define WELEMS ((size_t)NE * ND * NF)   // 33.55M elems per ffn weight

// ---------------- scratch ----------------------------------------------------
__device__ __half g_s16[NT * ND];
__device__ __half g_qkv[3 * NT * ND];
__device__ __half g_a16[NT * ND];
__device__ __half g_g16[NT * ND];
__device__ __half g_x16[NT * ND];
__device__ __half g_h16[(size_t)NT * NF];
__device__ __half g_wqkv[3 * ND * ND];
__device__ __half g_wg[ND * ND];
__device__ __half g_wo[ND * ND];
__device__ __half g_w116[WELEMS];
__device__ __half g_w216[WELEMS];
__device__ float g_scalef[NB * NH * NS];
__device__ float g_xres[NT * ND];
__device__ float g_x[NT * ND];
__device__ float g_z[NT * ND];
__device__ float g_h[(size_t)NT * NF];
__device__ int g_esel[NT];
__device__ int g_perm[NT];
__device__ int g_eid[NT];
__device__ int g_off[NE];
__device__ int g_cnt[NE];

// ---------------- helpers ----------------------------------------------------
__device__ __forceinline__ uint32_t s2u(const void* p) {
    uint32_t a;
    asm("{ .reg .u64 t; cvta.to.shared.u64 t, %1; cvt.u32.u64 %0, t; }" : "=r"(a) : "l"(p));
    return a;
}
__device__ __forceinline__ unsigned pkh(float a, float b) {
    __half2 hh = __floats2half2_rn(a, b);
    return *reinterpret_cast<unsigned*>(&hh);
}
__device__ __forceinline__ void ldm_x4(unsigned* r, uint32_t addr) {
    asm volatile("ldmatrix.sync.aligned.m8n8.x4.shared.b16 {%0,%1,%2,%3}, [%4];"
        : "=r"(r[0]), "=r"(r[1]), "=r"(r[2]), "=r"(r[3]) : "r"(addr));
}
__device__ __forceinline__ void ldm_x4_t(unsigned* r, uint32_t addr) {
    asm volatile("ldmatrix.sync.aligned.m8n8.x4.trans.shared.b16 {%0,%1,%2,%3}, [%4];"
        : "=r"(r[0]), "=r"(r[1]), "=r"(r[2]), "=r"(r[3]) : "r"(addr));
}
__device__ __forceinline__ void mma16816(float* c, const unsigned* a, const unsigned* b) {
    asm volatile(
        "mma.sync.aligned.m16n8k16.row.col.f32.f16.f16.f32 "
        "{%0,%1,%2,%3}, {%4,%5,%6,%7}, {%8,%9}, {%0,%1,%2,%3};"
        : "+f"(c[0]), "+f"(c[1]), "+f"(c[2]), "+f"(c[3])
        : "r"(a[0]), "r"(a[1]), "r"(a[2]), "r"(a[3]), "r"(b[0]), "r"(b[1]));
}
__device__ __forceinline__ void cpa(uint32_t d, const void* s, int szvalid) {
    asm volatile("cp.async.cg.shared.global [%0], [%1], 16, %2;"
        :: "r"(d), "l"(__cvta_generic_to_global(s)), "r"(szvalid));
}

__device__ __forceinline__ void cvt8(const float* __restrict__ in, __half* __restrict__ o,
                                     size_t i)
{
    float4 a = *(const float4*)(in + i);
    float4 b = *(const float4*)(in + i + 4);
    unsigned h[4];
    h[0] = pkh(a.x, a.y); h[1] = pkh(a.z, a.w);
    h[2] = pkh(b.x, b.y); h[3] = pkh(b.z, b.w);
    *(uint4*)(o + i) = *(uint4*)h;
}

// ---------------- pipelined mma.sync fp16 GEMM (4-stage, 1 sync/chunk) --------
// C[128,128] = A[M,K] @ B[K,N]; A fp16, B fp16.
// OP: 0 merged QKV (z=3 plane converts w1 via `extra`) | 1 gate | 2 ow (+src)
//     3 ffn1 gather +b1 | 4 ffn2
template <int OP>
__global__ void __launch_bounds__(256, 2) k_mm(
    const __half* __restrict__ Ah, const __half* __restrict__ B16,
    int K, int ldB,
    const float* __restrict__ bias, const float* __restrict__ extra,
    const float* __restrict__ extra2,
    __half* __restrict__ Oh, float* __restrict__ Of)
{
    if (OP == 0 && blockIdx.z == 3) {
        size_t base = (((size_t)blockIdx.y * 8 + blockIdx.x) * 256 + threadIdx.x) * 8;
        size_t stride = (size_t)128 * 256 * 8;
        for (size_t u = base; u < WELEMS; u += stride) cvt8(extra, g_w116, u);
        return;
    }

    extern __shared__ __align__(16) char sm[];
    __shared__ int rloc[TM];

    const int tid = threadIdx.x;
    const int lane = tid & 31, wid = tid >> 5;
    const int warp_m = wid >> 2, warp_n = wid & 3;
    const int row0 = blockIdx.y * TM, col0 = blockIdx.x * TN;
    const int e = blockIdx.z;
    int cnt = 0, off = 0;
    if (OP == 0) {
        B16 += (size_t)e * ND * ND;
        Oh += (size_t)e * NT * ND;
    }
    if (OP == 3 || OP == 4) {
        cnt = g_cnt[e]; off = g_off[e];
        if (row0 >= cnt) return;
        B16 += (size_t)e * K * ldB;
    }
    if (OP == 3) {
        if (tid < TM) {
            int gr = row0 + tid;
            rloc[tid] = (gr < cnt) ? g_perm[off + gr] : -1;
        }
        __syncthreads();
    }

    const int am = tid >> 1, ahalf = tid & 1;
    int arow;
    if (OP == 3) arow = rloc[am];
    else if (OP == 4) arow = min(off + row0 + am, NT - 1);
    else arow = row0 + am;
    const int apred = (arow >= 0) ? 16 : 0;
    const int arows = (arow >= 0) ? arow : 0;
    const char* gA = (const char*)(Ah + (size_t)arows * K + ahalf * 16);
    const int bk = tid >> 3, bseg = tid & 7;
    const char* gB16 = (const char*)(B16 + (size_t)bk * ldB + col0 + bseg * 16);

    const uint32_t ub = s2u(sm);
    const uint32_t aDst = ub + ST_A + am * 80 + ahalf * 32;
    const uint32_t bDst = ub + ST_B + bk * 272 + bseg * 32;

    auto issue = [&](int stage, int c) {
        uint32_t sb = stage * STAGE_BYTES;
        size_t ao = (size_t)c * KC * 2;
        size_t bo = (size_t)c * KC * ldB * 2;
        cpa(aDst + sb,      gA + ao,      apred);
        cpa(aDst + sb + 16, gA + ao + 16, apred);
        cpa(bDst + sb,      gB16 + bo,      16);
        cpa(bDst + sb + 16, gB16 + bo + 16, 16);
        asm volatile("cp.async.commit_group;");
    };

    float acc[16][4];
#pragma unroll
    for (int t = 0; t < 16; t++)
#pragma unroll
        for (int i = 0; i < 4; i++) acc[t][i] = 0.f;

    const int nch = K / KC;
#pragma unroll
    for (int s = 0; s < NST1 - 1; s++) issue(s, s);

    for (int c = 0; c < nch; c++) {
        asm volatile("cp.async.wait_group %0;" :: "n"(NST1 - 2));
        __syncthreads();
        // prefetch chunk c+NST1-1 into stage (c-1)%NST1 — just fully consumed
        int nc = c + NST1 - 1;
        if (nc < nch) issue(nc % NST1, nc);
        else asm volatile("cp.async.commit_group;");

        uint32_t sb = ub + (c % NST1) * STAGE_BYTES;
        uint32_t uA_ = sb + ST_A;
        uint32_t uB_ = sb + ST_B;
#pragma unroll
        for (int ks = 0; ks < 2; ks++) {
            unsigned b_[2][4];
#pragma unroll
            for (int nt = 0; nt < 2; nt++) {
                int krow = ks * 16 + (lane & 7) + ((lane >> 3) & 1) * 8;
                int ncol = warp_n * 32 + nt * 16 + (lane >> 4) * 8;
                uint32_t o = (uint32_t)(krow * B_STRIDE + ncol) * 2;
                ldm_x4_t(b_[nt], uB_ + o);
            }
#pragma unroll
            for (int mt = 0; mt < 4; mt++) {
                unsigned a_[4];
                int mrow = warp_m * 64 + mt * 16 + (lane & 15);
                int kcol = ks * 16 + (lane >> 4) * 8;
                uint32_t o = (uint32_t)(mrow * A_STRIDE + kcol) * 2;
                ldm_x4(a_, uA_ + o);
#pragma unroll
                for (int nt = 0; nt < 2; nt++)
#pragma unroll
                    for (int j = 0; j < 2; j++)
                        mma16816(acc[mt * 4 + nt * 2 + j], a_, b_[nt] + j * 2);
            }
        }
    }

    // ---- epilogue ----
    float rs = 0.f;
    if (OP == 4) rs = extra2[e];
#pragma unroll
    for (int mt = 0; mt < 4; mt++)
#pragma unroll
        for (int nt = 0; nt < 2; nt++)
#pragma unroll
            for (int j = 0; j < 2; j++) {
                float* cc = acc[mt * 4 + nt * 2 + j];
                int lcol = warp_n * 32 + nt * 16 + j * 8 + (lane & 3) * 2;
                int gcol = col0 + lcol;
#pragma unroll
                for (int half = 0; half < 2; half++) {
                    int lrow = warp_m * 64 + mt * 16 + (lane >> 2) + half * 8;
                    int gr = row0 + lrow;
                    float v0 = cc[half * 2], v1 = cc[half * 2 + 1];
                    if (OP == 0) {
                        size_t base = (size_t)gr * ND + gcol;
                        *(unsigned*)(Oh + base) = pkh(v0, v1);
                    } else if (OP == 1) {
                        size_t base = (size_t)gr * ND + gcol;
                        float g0 = 1.f / (1.f + expf(-(v0 + bias[gcol])));
                        float g1 = 1.f / (1.f + expf(-(v1 + bias[gcol + 1])));
                        float a0 = __half2float(Ah[base]);
                        float a1 = __half2float(Ah[base + 1]);
                        *(unsigned*)(Oh + base) = pkh(a0 * g0, a1 * g1);
                    } else if (OP == 2) {
                        size_t base = (size_t)gr * ND + gcol;
                        float2 o2;
                        o2.x = extra[base] + v0;
                        o2.y = extra[base + 1] + v1;
                        *(float2*)(Of + base) = o2;
                    } else if (OP == 3) {
                        if (gr < cnt) {
                            size_t base = (size_t)(off + gr) * NF + gcol;
                            float2 o2;
                            o2.x = v0 + bias[e * NF + gcol];
                            o2.y = v1 + bias[e * NF + gcol + 1];
                            *(float2*)(Of + base) = o2;
                        }
                    } else if (OP == 4) {
                        if (gr < cnt) {
                            int t = g_perm[off + gr];
                            size_t bx = (size_t)t * ND + gcol;
                            float2 o2;
                            o2.x = 2.f * extra[bx] + rs * (v0 + bias[e * ND + gcol]);
                            o2.y = 2.f * extra[bx + 1] + rs * (v1 + bias[e * ND + gcol + 1]);
                            *(float2*)(Of + bx) = o2;
                        }
                    }
                }
            }
}

// ---------------- mma.sync flash attention (fp16, cp.async 2-stage KV) --------
// z=0 plane: flash attention.  z=1 plane: stream-convert w2 fp32 -> fp16.
__global__ void __launch_bounds__(128, 4) k_flash(const float* __restrict__ w2src)
{
    if (blockIdx.z == 1) {
        size_t cid = (size_t)blockIdx.y * 16 + blockIdx.x;  // 512 CTAs
        size_t base = (cid * 128 + threadIdx.x) * 8;
        size_t stride = (size_t)512 * 128 * 8;
        for (size_t u = base; u < WELEMS; u += stride) cvt8(w2src, g_w216, u);
        return;
    }

    extern __shared__ __align__(16) char fsm[];
    const int tid = threadIdx.x, lane = tid & 31, warpm = tid >> 5;
    const int bh = blockIdx.y, b = bh >> 4, h = bh & 15;
    const int row0 = blockIdx.x * 64;

    const __half* Qg = g_qkv;
    const __half* Kg = g_qkv + (size_t)NT * ND;
    const __half* Vg = g_qkv + (size_t)2 * NT * ND;

    const uint32_t ubase = s2u(fsm);
    const int m = tid >> 1, half = tid & 1;

    auto issue_kv = [&](int buf, int jt) {
        size_t gsrc = (size_t)(b * NS + jt * 64 + m) * ND + h * 64 + half * 32;
        uint32_t dk = ubase + F_KV0 + buf * 18432 + m * 144 + half * 64;
        uint32_t dv = dk + 9216;
        const char* pk = (const char*)(Kg + gsrc);
        const char* pv = (const char*)(Vg + gsrc);
#pragma unroll
        for (int i = 0; i < 4; i++) {
            cpa(dk + i * 16, pk + i * 16, 16);
            cpa(dv + i * 16, pv + i * 16, 16);
        }
        asm volatile("cp.async.commit_group;");
    };

    // Q tile: apply scale, store fp16
    {
        float sc = g_scalef[bh * NS + row0 + m];
        const __half* src_ = Qg + (size_t)(b * NS + row0 + m) * ND + h * 64 + half * 32;
        char* dq = fsm + F_Q + m * 144 + half * 64;
#pragma unroll
        for (int i = 0; i < 4; i++) {
            __half qb[8];
            *(uint4*)qb = *(const uint4*)(src_ + i * 8);
            unsigned o4[4];
#pragma unroll
            for (int j = 0; j < 4; j++)
                o4[j] = pkh(__half2float(qb[2 * j]) * sc, __half2float(qb[2 * j + 1]) * sc);
            *(uint4*)(dq + i * 16) = *(uint4*)o4;
        }
    }

    issue_kv(0, 0);

    const uint32_t uQ = ubase + F_Q;
    const uint32_t qa_off = ((warpm * 16 + (lane & 15)) * F_STRIDE + ((lane >> 4) & 1) * 8) * 2;
    const uint32_t ka_off = (((lane & 7) + ((lane >> 4) << 3)) * F_STRIDE + ((lane >> 3) & 1) * 8) * 2;
    const uint32_t va_off = (((lane & 7) + ((lane >> 3) & 1) * 8) * F_STRIDE + ((lane >> 4) & 1) * 8) * 2;

    float oacc[8][4];
#pragma unroll
    for (int t = 0; t < 8; t++)
#pragma unroll
        for (int i = 0; i < 4; i++) oacc[t][i] = 0.f;
    float mi0 = -1e30f, mi1 = -1e30f, li0 = 0.f, li1 = 0.f;

    const int njt = NS / 64;
    for (int jt = 0; jt < njt; jt++) {
        asm volatile("cp.async.wait_group 0;");
        __syncthreads();
        if (jt + 1 < njt) issue_kv((jt + 1) & 1, jt + 1);

        const uint32_t uK = ubase + F_KV0 + (jt & 1) * 18432;
        const uint32_t uV = uK + 9216;

        float sacc[8][4];
#pragma unroll
        for (int t = 0; t < 8; t++)
#pragma unroll
            for (int i = 0; i < 4; i++) sacc[t][i] = 0.f;
#pragma unroll
        for (int ks = 0; ks < 4; ks++) {
            unsigned q4[4];
            ldm_x4(q4, uQ + qa_off + ks * 32);
#pragma unroll
            for (int np = 0; np < 4; np++) {
                unsigned k4[4];
                uint32_t o = ka_off + (uint32_t)(np * 16 * F_STRIDE + ks * 16) * 2;
                ldm_x4(k4, uK + o);
                mma16816(sacc[2 * np],     q4, k4);
                mma16816(sacc[2 * np + 1], q4, k4 + 2);
            }
        }

        float rm0 = -1e30f, rm1 = -1e30f;
#pragma unroll
        for (int j = 0; j < 8; j++) {
            rm0 = fmaxf(rm0, fmaxf(sacc[j][0], sacc[j][1]));
            rm1 = fmaxf(rm1, fmaxf(sacc[j][2], sacc[j][3]));
        }
        rm0 = fmaxf(rm0, __shfl_xor_sync(0xffffffffu, rm0, 1));
        rm0 = fmaxf(rm0, __shfl_xor_sync(0xffffffffu, rm0, 2));
        rm1 = fmaxf(rm1, __shfl_xor_sync(0xffffffffu, rm1, 1));
        rm1 = fmaxf(rm1, __shfl_xor_sync(0xffffffffu, rm1, 2));
        float mn0 = fmaxf(mi0, rm0), mn1 = fmaxf(mi1, rm1);
        float al0 = expf(mi0 - mn0), al1 = expf(mi1 - mn1);
        float rs0 = 0.f, rs1 = 0.f;
#pragma unroll
        for (int j = 0; j < 8; j++) {
            sacc[j][0] = expf(sacc[j][0] - mn0); rs0 += sacc[j][0];
            sacc[j][1] = expf(sacc[j][1] - mn0); rs0 += sacc[j][1];
            sacc[j][2] = expf(sacc[j][2] - mn1); rs1 += sacc[j][2];
            sacc[j][3] = expf(sacc[j][3] - mn1); rs1 += sacc[j][3];
        }
        rs0 += __shfl_xor_sync(0xffffffffu, rs0, 1);
        rs0 += __shfl_xor_sync(0xffffffffu, rs0, 2);
        rs1 += __shfl_xor_sync(0xffffffffu, rs1, 1);
        rs1 += __shfl_xor_sync(0xffffffffu, rs1, 2);
        li0 = li0 * al0 + rs0; li1 = li1 * al1 + rs1;
        mi0 = mn0; mi1 = mn1;
#pragma unroll
        for (int t = 0; t < 8; t++) {
            oacc[t][0] *= al0; oacc[t][1] *= al0;
            oacc[t][2] *= al1; oacc[t][3] *= al1;
        }

#pragma unroll
        for (int kb = 0; kb < 4; kb++) {
            unsigned pa[4];
            pa[0] = pkh(sacc[2 * kb][0],     sacc[2 * kb][1]);
            pa[1] = pkh(sacc[2 * kb][2],     sacc[2 * kb][3]);
            pa[2] = pkh(sacc[2 * kb + 1][0], sacc[2 * kb + 1][1]);
            pa[3] = pkh(sacc[2 * kb + 1][2], sacc[2 * kb + 1][3]);
#pragma unroll
            for (int ndp = 0; ndp < 4; ndp++) {
                unsigned v4[4];
                uint32_t o = va_off + (uint32_t)(kb * 16 * F_STRIDE + ndp * 16) * 2;
                ldm_x4_t(v4, uV + o);
                mma16816(oacc[2 * ndp],     pa, v4);
                mma16816(oacc[2 * ndp + 1], pa, v4 + 2);
            }
        }
    }

    float inv0 = 1.f / li0, inv1 = 1.f / li1;
    int r = row0 + warpm * 16 + (lane >> 2);
    int cbase = h * 64 + (lane & 3) * 2;
#pragma unroll
    for (int dt = 0; dt < 8; dt++) {
        size_t idx = (size_t)(b * NS + r) * ND + cbase + dt * 8;
        *(unsigned*)(g_a16 + idx) = pkh(oacc[dt][0] * inv0, oacc[dt][1] * inv0);
        idx += (size_t)8 * ND;
        *(unsigned*)(g_a16 + idx) = pkh(oacc[dt][2] * inv1, oacc[dt][3] * inv1);
    }
}

// ---------------- reductions --------------------------------------------------
__device__ __forceinline__ void blk_reduce2(float& s, float& q)
{
    __shared__ float ss[8], sq[8];
#pragma unroll
    for (int o = 16; o; o >>= 1) {
        s += __shfl_xor_sync(0xffffffffu, s, o);
        q += __shfl_xor_sync(0xffffffffu, q, o);
    }
    int w = threadIdx.x >> 5, l = threadIdx.x & 31;
    if (l == 0) { ss[w] = s; sq[w] = q; }
    __syncthreads();
    s = (l < 8) ? ss[l] : 0.f;
    q = (l < 8) ? sq[l] : 0.f;
#pragma unroll
    for (int o = 4; o; o >>= 1) {
        s += __shfl_xor_sync(0xffffffffu, s, o);
        q += __shfl_xor_sync(0xffffffffu, q, o);
    }
    s = __shfl_sync(0xffffffffu, s, 0);
    q = __shfl_sync(0xffffffffu, q, 0);
}

// ---------------- conversions -------------------------------------------------
__global__ __launch_bounds__(256) void k_cvt_small(
    const float* __restrict__ src, const float* __restrict__ qw,
    const float* __restrict__ kw, const float* __restrict__ vw,
    const float* __restrict__ gw, const float* __restrict__ ow)
{
    size_t u = ((size_t)blockIdx.x * 256 + threadIdx.x) * 8;
    const size_t M = (size_t)ND * ND;
    if (u < 2 * M) {
        cvt8(src, g_s16, u);
    } else if (u < 5 * M) {
        size_t v = u - 2 * M;
        if (v < M) cvt8(qw, g_wqkv, v);
        else if (v < 2 * M) cvt8(kw, g_wqkv + M, v - M);
        else cvt8(vw, g_wqkv + 2 * M, v - 2 * M);
    } else if (u < 6 * M) {
        cvt8(gw, g_wg, u - 5 * M);
    } else {
        cvt8(ow, g_wo, u - 6 * M);
    }
}

// ---------------- elementwise -------------------------------------------------
__global__ __launch_bounds__(256) void k_qscale(const float* __restrict__ sw)
{
    int wid = blockIdx.x * 8 + (threadIdx.x >> 5);
    int lane = threadIdx.x & 31;
    int h = wid & (NH - 1), t = wid >> 4;
    size_t i0 = (size_t)t * ND + h * 64 + lane;
    float q0 = __half2float(g_qkv[i0]);
    float q1 = __half2float(g_qkv[i0 + 32]);
    float s = q0 * sw[h * 64 + lane] + q1 * sw[h * 64 + lane + 32];
#pragma unroll
    for (int o = 16; o; o >>= 1) s += __shfl_xor_sync(0xffffffffu, s, o);
    if (lane == 0) {
        float sig = 1.f / (1.f + expf(-s));
        int b = t >> 10, si = t & (NS - 1);
        g_scalef[(b * NH + h) * NS + si] = 0.25f * sig;
    }
}

__global__ __launch_bounds__(256) void k_ln1(const float* __restrict__ g,
                                             const float* __restrict__ b)
{
    size_t r = blockIdx.x;
    const float* in = g_xres + r * ND;
    float x[4];
    float s = 0.f, q = 0.f;
#pragma unroll
    for (int l = 0; l < 4; l++) {
        x[l] = in[threadIdx.x + l * 256];
        s += x[l]; q += x[l] * x[l];
    }
    blk_reduce2(s, q);
    float mean = s * (1.f / ND);
    float var = q * (1.f / ND) - mean * mean;
    float rstd = rsqrtf(var + 1e-5f);
#pragma unroll
    for (int l = 0; l < 4; l++) {
        int c = threadIdx.x + l * 256;
        float v = (x[l] - mean) * rstd * g[c] + b[c];
        g_x[r * ND + c] = v;
        g_x16[r * ND + c] = __float2half_rn(v);
    }
}

__global__ __launch_bounds__(256) void k_ln_out(const float* __restrict__ g,
                                                const float* __restrict__ b,
                                                float* __restrict__ out)
{
    size_t r = blockIdx.x;
    const float* in = g_z + r * ND;
    float x[4];
    float s = 0.f, q = 0.f;
#pragma unroll
    for (int l = 0; l < 4; l++) {
        x[l] = in[threadIdx.x + l * 256];
        s += x[l]; q += x[l] * x[l];
    }
    blk_reduce2(s, q);
    float mean = s * (1.f / ND);
    float var = q * (1.f / ND) - mean * mean;
    float rstd = rsqrtf(var + 1e-5f);
#pragma unroll
    for (int l = 0; l < 4; l++) {
        int c = threadIdx.x + l * 256;
        out[r * ND + c] = (x[l] - mean) * rstd * g[c] + b[c];
    }
}

__global__ __launch_bounds__(256) void k_route(const float* __restrict__ gw,
                                               const float* __restrict__ gb)
{
    __shared__ float lg[NE];
    int t = blockIdx.x;
    int w = threadIdx.x >> 5, lane = threadIdx.x & 31;
    const float* x = g_x + (size_t)t * ND;
    float s = 0.f;
    for (int d = lane; d < ND; d += 32) s += x[d] * gw[d * NE + w];
#pragma unroll
    for (int o = 16; o; o >>= 1) s += __shfl_xor_sync(0xffffffffu, s, o);
    if (lane == 0) lg[w] = s + gb[w];
    __syncthreads();
    if (threadIdx.x == 0) {
        int i1 = 0; float v1 = lg[0];
#pragma unroll
        for (int e = 1; e < NE; e++) if (lg[e] > v1) { v1 = lg[e]; i1 = e; }
        int i2 = -1; float v2 = -1e30f;
#pragma unroll
        for (int e = 0; e < NE; e++) if (e != i1 && lg[e] > v2) { v2 = lg[e]; i2 = e; }
        g_esel[t] = (i1 > i2) ? i1 : i2;
    }
}

__global__ void k_scatter()
{
    __shared__ int scnt[NE], soff[NE], scur[NE];
    int tid = threadIdx.x;
    if (tid < NE) scnt[tid] = 0;
    __syncthreads();
    for (int t = tid; t < NT; t += 1024) atomicAdd(&scnt[g_esel[t]], 1);
    __syncthreads();
    if (tid == 0) {
        int r = 0;
        for (int e = 0; e < NE; e++) { soff[e] = r; r += scnt[e]; }
    }
    __syncthreads();
    if (tid < NE) { scur[tid] = soff[tid]; g_off[tid] = soff[tid]; g_cnt[tid] = scnt[tid]; }
    __syncthreads();
    for (int t = tid; t < NT; t += 1024) {
        int e = g_esel[t];
        int pos = atomicAdd(&scur[e], 1);
        g_perm[pos] = t;
        g_eid[pos] = e;
    }
}

__global__ __launch_bounds__(256) void k_lngelu(const float* __restrict__ lng,
                                                const float* __restrict__ lnb)
{
    int row = blockIdx.x;
    int e = g_eid[row];
    const float* hp = g_h + (size_t)row * NF;
    float x[16];
    float s = 0.f, q = 0.f;
#pragma unroll
    for (int l = 0; l < 16; l++) {
        x[l] = hp[threadIdx.x + l * 256];
        s += x[l]; q += x[l] * x[l];
    }
    blk_reduce2(s, q);
    float mean = s * (1.f / NF);
    float var = q * (1.f / NF) - mean * mean;
    float rstd = rsqrtf(var + 1e-5f);
    const float* g = lng + (size_t)e * NF;
    const float* b = lnb + (size_t)e * NF;
#pragma unroll
    for (int l = 0; l < 16; l++) {
        int c = threadIdx.x + l * 256;
        float hn = (x[l] - mean) * rstd * g[c] + b[c];
        float gel = 0.5f * hn * (1.f + erff(hn * 0.70710678118654752f));
        g_h16[(size_t)row * NF + c] = __float2half_rn(gel);
    }
}

// ---------------- launch ------------------------------------------------------
extern "C" void kernel_launch(void* const* d_in, const int* in_sizes, int n_in,
                              void* d_out, int out_size)
{
    (void)in_sizes; (void)n_in; (void)out_size;
    const float* src        = (const float*)d_in[0];
    const float* qw         = (const float*)d_in[1];
    const float* kw         = (const float*)d_in[2];
    const float* vw         = (const float*)d_in[3];
    const float* ow         = (const float*)d_in[4];
    const float* gate_w     = (const float*)d_in[5];
    const float* gate_b     = (const float*)d_in[6];
    const float* scale_w    = (const float*)d_in[7];
    const float* n1_g       = (const float*)d_in[8];
    const float* n1_b       = (const float*)d_in[9];
    const float* n2_g       = (const float*)d_in[10];
    const float* n2_b       = (const float*)d_in[11];
    const float* moe_gate_w = (const float*)d_in[12];
    const float* moe_gate_b = (const float*)d_in[13];
    const float* w1         = (const float*)d_in[14];
    const float* b1         = (const float*)d_in[15];
    const float* ln_g       = (const float*)d_in[16];
    const float* ln_b       = (const float*)d_in[17];
    const float* w2         = (const float*)d_in[18];
    const float* b2         = (const float*)d_in[19];
    const float* res_scale  = (const float*)d_in[20];
    float* out = (float*)d_out;

    cudaFuncSetAttribute((const void*)k_mm<0>, cudaFuncAttributeMaxDynamicSharedMemorySize, GEMM_SMEM);
    cudaFuncSetAttribute((const void*)k_mm<1>, cudaFuncAttributeMaxDynamicSharedMemorySize, GEMM_SMEM);
    cudaFuncSetAttribute((const void*)k_mm<2>, cudaFuncAttributeMaxDynamicSharedMemorySize, GEMM_SMEM);
    cudaFuncSetAttribute((const void*)k_mm<3>, cudaFuncAttributeMaxDynamicSharedMemorySize, GEMM_SMEM);
    cudaFuncSetAttribute((const void*)k_mm<4>, cudaFuncAttributeMaxDynamicSharedMemorySize, GEMM_SMEM);
    cudaFuncSetAttribute((const void*)k_flash, cudaFuncAttributeMaxDynamicSharedMemorySize, FLASH_SMEM);

    __half *s16, *qkv, *a16, *g16, *x16, *h16, *wqkv, *wg, *wo, *w116, *w216;
    float *xres, *x, *z, *hbuf;
    cudaGetSymbolAddress((void**)&s16, g_s16);
    cudaGetSymbolAddress((void**)&qkv, g_qkv);
    cudaGetSymbolAddress((void**)&a16, g_a16);
    cudaGetSymbolAddress((void**)&g16, g_g16);
    cudaGetSymbolAddress((void**)&x16, g_x16);
    cudaGetSymbolAddress((void**)&h16, g_h16);
    cudaGetSymbolAddress((void**)&wqkv, g_wqkv);
    cudaGetSymbolAddress((void**)&wg, g_wg);
    cudaGetSymbolAddress((void**)&wo, g_wo);
    cudaGetSymbolAddress((void**)&w116, g_w116);
    cudaGetSymbolAddress((void**)&w216, g_w216);
    cudaGetSymbolAddress((void**)&xres, g_xres);
    cudaGetSymbolAddress((void**)&x, g_x);
    cudaGetSymbolAddress((void**)&z, g_z);
    cudaGetSymbolAddress((void**)&hbuf, g_h);

    k_cvt_small<<<7 * 1024 * 1024 / 2048, 256>>>(src, qw, kw, vw, gate_w, ow);

    k_mm<0><<<dim3(ND / TN, NT / TM, 4), 256, GEMM_SMEM>>>(s16, wqkv,
        ND, ND, nullptr, w1, nullptr, qkv, nullptr);
    k_qscale<<<(NT * NH) / 8, 256>>>(scale_w);
    k_flash<<<dim3(NS / 64, NB * NH, 2), 128, FLASH_SMEM>>>(w2);
    k_mm<1><<<dim3(ND / TN, NT / TM), 256, GEMM_SMEM>>>(a16, wg,
        ND, ND, gate_b, nullptr, nullptr, g16, nullptr);
    k_mm<2><<<dim3(ND / TN, NT / TM), 256, GEMM_SMEM>>>(g16, wo,
        ND, ND, nullptr, src, nullptr, nullptr, xres);
    k_ln1<<<NT, 256>>>(n1_g, n1_b);
    k_route<<<NT, 256>>>(moe_gate_w, moe_gate_b);
    k_scatter<<<1, 1024>>>();
    k_mm<3><<<dim3(NF / TN, NT / TM, NE), 256, GEMM_SMEM>>>(x16, w116,
        ND, NF, b1, nullptr, nullptr, nullptr, hbuf);
    k_lngelu<<<NT, 256>>>(ln_g, ln_b);
    k_mm<4><<<dim3(ND / TN, NT / TM, NE), 256, GEMM_SMEM>>>(h16, w216,
        NF, ND, b2, x, res_scale, nullptr, z);
    k_ln_out<<<NT, 256>>>(n2_g, n2_b, out);
}

// round 12
// speedup vs baseline: 1.4556x; 1.4556x over previous
#include <cuda_runtime.h>
#include <cuda_fp16.h>
#include <math.h>
#include <stdint.h>

#define NB 2
#define NS 1024
#define ND 1024
#define NH 16
#define NE 8
#define NF 4096
#define NT 2048

#define TM 128
#define TN 128
#define KC 32
#define A_STRIDE 40    // fp16 elems per A smem row (80B)
#define B_STRIDE 136   // fp16 elems per B smem row (272B)

// 4-stage fp16 pipeline
#define ST_A 0
#define ST_B 10240
#define STAGE_BYTES 18944
#define NST1 4
#define GEMM_SMEM (NST1 * STAGE_BYTES)

#define F_STRIDE 72    // flash smem row stride (144B)
#define F_Q 0
#define F_K 9216
#define F_V 18432
#define FLASH_SMEM 27648

#define WELEMS ((size_t)NE * ND * NF)   // 33.55M elems per ffn weight

// ---------------- scratch ----------------------------------------------------
__device__ __half g_s16[NT * ND];
__device__ __half g_qkv[3 * NT * ND];
__device__ __half g_a16[NT * ND];
__device__ __half g_g16[NT * ND];
__device__ __half g_x16[NT * ND];
__device__ __half g_h16[(size_t)NT * NF];
__device__ __half g_wqkv[3 * ND * ND];
__device__ __half g_wg[ND * ND];
__device__ __half g_wo[ND * ND];
__device__ __half g_w116[WELEMS];
__device__ __half g_w216[WELEMS];
__device__ float g_scalef[NB * NH * NS];
__device__ float g_xres[NT * ND];
__device__ float g_x[NT * ND];
__device__ float g_z[NT * ND];
__device__ float g_h[(size_t)NT * NF];
__device__ int g_esel[NT];
__device__ int g_perm[NT];
__device__ int g_eid[NT];
__device__ int g_off[NE];
__device__ int g_cnt[NE];

// ---------------- helpers ----------------------------------------------------
__device__ __forceinline__ uint32_t s2u(const void* p) {
    uint32_t a;
    asm("{ .reg .u64 t; cvta.to.shared.u64 t, %1; cvt.u32.u64 %0, t; }" : "=r"(a) : "l"(p));
    return a;
}
__device__ __forceinline__ unsigned pkh(float a, float b) {
    __half2 hh = __floats2half2_rn(a, b);
    return *reinterpret_cast<unsigned*>(&hh);
}
__device__ __forceinline__ void ldm_x4(unsigned* r, uint32_t addr) {
    asm volatile("ldmatrix.sync.aligned.m8n8.x4.shared.b16 {%0,%1,%2,%3}, [%4];"
        : "=r"(r[0]), "=r"(r[1]), "=r"(r[2]), "=r"(r[3]) : "r"(addr));
}
__device__ __forceinline__ void ldm_x4_t(unsigned* r, uint32_t addr) {
    asm volatile("ldmatrix.sync.aligned.m8n8.x4.trans.shared.b16 {%0,%1,%2,%3}, [%4];"
        : "=r"(r[0]), "=r"(r[1]), "=r"(r[2]), "=r"(r[3]) : "r"(addr));
}
__device__ __forceinline__ void mma16816(float* c, const unsigned* a, const unsigned* b) {
    asm volatile(
        "mma.sync.aligned.m16n8k16.row.col.f32.f16.f16.f32 "
        "{%0,%1,%2,%3}, {%4,%5,%6,%7}, {%8,%9}, {%0,%1,%2,%3};"
        : "+f"(c[0]), "+f"(c[1]), "+f"(c[2]), "+f"(c[3])
        : "r"(a[0]), "r"(a[1]), "r"(a[2]), "r"(a[3]), "r"(b[0]), "r"(b[1]));
}
__device__ __forceinline__ void cpa(uint32_t d, const void* s, int szvalid) {
    asm volatile("cp.async.cg.shared.global [%0], [%1], 16, %2;"
        :: "r"(d), "l"(__cvta_generic_to_global(s)), "r"(szvalid));
}

__device__ __forceinline__ void cvt8(const float* __restrict__ in, __half* __restrict__ o,
                                     size_t i)
{
    float4 a = *(const float4*)(in + i);
    float4 b = *(const float4*)(in + i + 4);
    unsigned h[4];
    h[0] = pkh(a.x, a.y); h[1] = pkh(a.z, a.w);
    h[2] = pkh(b.x, b.y); h[3] = pkh(b.z, b.w);
    *(uint4*)(o + i) = *(uint4*)h;
}

// ---------------- pipelined mma.sync fp16 GEMM (4-stage, R10 schedule) --------
// OP: 0 merged QKV (z=3 plane converts w1 via `extra`) | 1 gate | 2 ow (+src)
//     3 ffn1 gather +b1 | 4 ffn2
template <int OP>
__global__ void __launch_bounds__(256, 2) k_mm(
    const __half* __restrict__ Ah, const __half* __restrict__ B16,
    int K, int ldB,
    const float* __restrict__ bias, const float* __restrict__ extra,
    const float* __restrict__ extra2,
    __half* __restrict__ Oh, float* __restrict__ Of)
{
    if (OP == 0 && blockIdx.z == 3) {
        size_t base = (((size_t)blockIdx.y * 8 + blockIdx.x) * 256 + threadIdx.x) * 8;
        size_t stride = (size_t)128 * 256 * 8;
        for (size_t u = base; u < WELEMS; u += stride) cvt8(extra, g_w116, u);
        return;
    }

    extern __shared__ __align__(16) char sm[];
    __shared__ int rloc[TM];

    const int tid = threadIdx.x;
    const int lane = tid & 31, wid = tid >> 5;
    const int warp_m = wid >> 2, warp_n = wid & 3;
    const int row0 = blockIdx.y * TM, col0 = blockIdx.x * TN;
    const int e = blockIdx.z;
    int cnt = 0, off = 0;
    if (OP == 0) {
        B16 += (size_t)e * ND * ND;
        Oh += (size_t)e * NT * ND;
    }
    if (OP == 3 || OP == 4) {
        cnt = g_cnt[e]; off = g_off[e];
        if (row0 >= cnt) return;
        B16 += (size_t)e * K * ldB;
    }
    if (OP == 3) {
        if (tid < TM) {
            int gr = row0 + tid;
            rloc[tid] = (gr < cnt) ? g_perm[off + gr] : -1;
        }
        __syncthreads();
    }

    const int am = tid >> 1, ahalf = tid & 1;
    int arow;
    if (OP == 3) arow = rloc[am];
    else if (OP == 4) arow = min(off + row0 + am, NT - 1);
    else arow = row0 + am;
    const int apred = (arow >= 0) ? 16 : 0;
    const int arows = (arow >= 0) ? arow : 0;
    const char* gA = (const char*)(Ah + (size_t)arows * K + ahalf * 16);
    const int bk = tid >> 3, bseg = tid & 7;
    const char* gB16 = (const char*)(B16 + (size_t)bk * ldB + col0 + bseg * 16);

    const uint32_t ub = s2u(sm);
    const uint32_t aDst = ub + ST_A + am * 80 + ahalf * 32;
    const uint32_t bDst = ub + ST_B + bk * 272 + bseg * 32;

    auto issue = [&](int stage, int c) {
        uint32_t sb = stage * STAGE_BYTES;
        size_t ao = (size_t)c * KC * 2;
        size_t bo = (size_t)c * KC * ldB * 2;
        cpa(aDst + sb,      gA + ao,      apred);
        cpa(aDst + sb + 16, gA + ao + 16, apred);
        cpa(bDst + sb,      gB16 + bo,      16);
        cpa(bDst + sb + 16, gB16 + bo + 16, 16);
        asm volatile("cp.async.commit_group;");
    };

    float acc[16][4];
#pragma unroll
    for (int t = 0; t < 16; t++)
#pragma unroll
        for (int i = 0; i < 4; i++) acc[t][i] = 0.f;

    const int nch = K / KC;
#pragma unroll
    for (int s = 0; s < NST1; s++) issue(s, s);

    for (int c = 0; c < nch; c++) {
        asm volatile("cp.async.wait_group %0;" :: "n"(NST1 - 1));
        __syncthreads();
        uint32_t sb = ub + (c % NST1) * STAGE_BYTES;
        uint32_t uA_ = sb + ST_A;
        uint32_t uB_ = sb + ST_B;
#pragma unroll
        for (int ks = 0; ks < 2; ks++) {
            unsigned b_[2][4];
#pragma unroll
            for (int nt = 0; nt < 2; nt++) {
                int krow = ks * 16 + (lane & 7) + ((lane >> 3) & 1) * 8;
                int ncol = warp_n * 32 + nt * 16 + (lane >> 4) * 8;
                uint32_t o = (uint32_t)(krow * B_STRIDE + ncol) * 2;
                ldm_x4_t(b_[nt], uB_ + o);
            }
#pragma unroll
            for (int mt = 0; mt < 4; mt++) {
                unsigned a_[4];
                int mrow = warp_m * 64 + mt * 16 + (lane & 15);
                int kcol = ks * 16 + (lane >> 4) * 8;
                uint32_t o = (uint32_t)(mrow * A_STRIDE + kcol) * 2;
                ldm_x4(a_, uA_ + o);
#pragma unroll
                for (int nt = 0; nt < 2; nt++)
#pragma unroll
                    for (int j = 0; j < 2; j++)
                        mma16816(acc[mt * 4 + nt * 2 + j], a_, b_[nt] + j * 2);
            }
        }
        __syncthreads();
        if (c + NST1 < nch) issue(c % NST1, c + NST1);
        else asm volatile("cp.async.commit_group;");
    }

    // ---- epilogue ----
    float rs = 0.f;
    if (OP == 4) rs = extra2[e];
#pragma unroll
    for (int mt = 0; mt < 4; mt++)
#pragma unroll
        for (int nt = 0; nt < 2; nt++)
#pragma unroll
            for (int j = 0; j < 2; j++) {
                float* cc = acc[mt * 4 + nt * 2 + j];
                int lcol = warp_n * 32 + nt * 16 + j * 8 + (lane & 3) * 2;
                int gcol = col0 + lcol;
#pragma unroll
                for (int half = 0; half < 2; half++) {
                    int lrow = warp_m * 64 + mt * 16 + (lane >> 2) + half * 8;
                    int gr = row0 + lrow;
                    float v0 = cc[half * 2], v1 = cc[half * 2 + 1];
                    if (OP == 0) {
                        size_t base = (size_t)gr * ND + gcol;
                        *(unsigned*)(Oh + base) = pkh(v0, v1);
                    } else if (OP == 1) {
                        size_t base = (size_t)gr * ND + gcol;
                        float g0 = 1.f / (1.f + expf(-(v0 + bias[gcol])));
                        float g1 = 1.f / (1.f + expf(-(v1 + bias[gcol + 1])));
                        float a0 = __half2float(Ah[base]);
                        float a1 = __half2float(Ah[base + 1]);
                        *(unsigned*)(Oh + base) = pkh(a0 * g0, a1 * g1);
                    } else if (OP == 2) {
                        size_t base = (size_t)gr * ND + gcol;
                        float2 o2;
                        o2.x = extra[base] + v0;
                        o2.y = extra[base + 1] + v1;
                        *(float2*)(Of + base) = o2;
                    } else if (OP == 3) {
                        if (gr < cnt) {
                            size_t base = (size_t)(off + gr) * NF + gcol;
                            float2 o2;
                            o2.x = v0 + bias[e * NF + gcol];
                            o2.y = v1 + bias[e * NF + gcol + 1];
                            *(float2*)(Of + base) = o2;
                        }
                    } else if (OP == 4) {
                        if (gr < cnt) {
                            int t = g_perm[off + gr];
                            size_t bx = (size_t)t * ND + gcol;
                            float2 o2;
                            o2.x = 2.f * extra[bx] + rs * (v0 + bias[e * ND + gcol]);
                            o2.y = 2.f * extra[bx + 1] + rs * (v1 + bias[e * ND + gcol + 1]);
                            *(float2*)(Of + bx) = o2;
                        }
                    }
                }
            }
}

// ---------------- mma.sync flash attention (fp16, R10 plain loads) ------------
// z=0 plane: flash attention.  z=1 plane: stream-convert w2 fp32 -> fp16.
__global__ void __launch_bounds__(128, 4) k_flash(const float* __restrict__ w2src)
{
    if (blockIdx.z == 1) {
        size_t cid = (size_t)blockIdx.y * 16 + blockIdx.x;  // 512 CTAs
        size_t base = (cid * 128 + threadIdx.x) * 8;
        size_t stride = (size_t)512 * 128 * 8;
        for (size_t u = base; u < WELEMS; u += stride) cvt8(w2src, g_w216, u);
        return;
    }

    extern __shared__ __align__(16) char fsm[];
    const int tid = threadIdx.x, lane = tid & 31, warpm = tid >> 5;
    const int bh = blockIdx.y, b = bh >> 4, h = bh & 15;
    const int row0 = blockIdx.x * 64;

    const __half* Qg = g_qkv;
    const __half* Kg = g_qkv + (size_t)NT * ND;
    const __half* Vg = g_qkv + (size_t)2 * NT * ND;

    {
        int m = tid >> 1, half = tid & 1;
        float sc = g_scalef[bh * NS + row0 + m];
        const __half* src_ = Qg + (size_t)(b * NS + row0 + m) * ND + h * 64 + half * 32;
        char* dq = fsm + F_Q + m * 144 + half * 64;
#pragma unroll
        for (int i = 0; i < 4; i++) {
            __half qb[8];
            *(uint4*)qb = *(const uint4*)(src_ + i * 8);
            unsigned o4[4];
#pragma unroll
            for (int j = 0; j < 4; j++)
                o4[j] = pkh(__half2float(qb[2 * j]) * sc, __half2float(qb[2 * j + 1]) * sc);
            *(uint4*)(dq + i * 16) = *(uint4*)o4;
        }
    }

    const uint32_t ubase = s2u(fsm);
    const uint32_t uQ = ubase + F_Q, uK = ubase + F_K, uV = ubase + F_V;

    const uint32_t qa_off = ((warpm * 16 + (lane & 15)) * F_STRIDE + ((lane >> 4) & 1) * 8) * 2;
    const uint32_t ka_off = (((lane & 7) + ((lane >> 4) << 3)) * F_STRIDE + ((lane >> 3) & 1) * 8) * 2;
    const uint32_t va_off = (((lane & 7) + ((lane >> 3) & 1) * 8) * F_STRIDE + ((lane >> 4) & 1) * 8) * 2;

    float oacc[8][4];
#pragma unroll
    for (int t = 0; t < 8; t++)
#pragma unroll
        for (int i = 0; i < 4; i++) oacc[t][i] = 0.f;
    float mi0 = -1e30f, mi1 = -1e30f, li0 = 0.f, li1 = 0.f;

    for (int jt = 0; jt < NS / 64; jt++) {
        __syncthreads();
        {
            int m = tid >> 1, half = tid & 1;
            size_t gsrc = (size_t)(b * NS + jt * 64 + m) * ND + h * 64 + half * 32;
            char* dk = fsm + F_K + m * 144 + half * 64;
            char* dv = fsm + F_V + m * 144 + half * 64;
#pragma unroll
            for (int i = 0; i < 4; i++) {
                *(uint4*)(dk + i * 16) = *(const uint4*)((const char*)(Kg + gsrc) + i * 16);
                *(uint4*)(dv + i * 16) = *(const uint4*)((const char*)(Vg + gsrc) + i * 16);
            }
        }
        __syncthreads();

        float sacc[8][4];
#pragma unroll
        for (int t = 0; t < 8; t++)
#pragma unroll
            for (int i = 0; i < 4; i++) sacc[t][i] = 0.f;
#pragma unroll
        for (int ks = 0; ks < 4; ks++) {
            unsigned q4[4];
            ldm_x4(q4, uQ + qa_off + ks * 32);
#pragma unroll
            for (int np = 0; np < 4; np++) {
                unsigned k4[4];
                uint32_t o = ka_off + (uint32_t)(np * 16 * F_STRIDE + ks * 16) * 2;
                ldm_x4(k4, uK + o);
                mma16816(sacc[2 * np],     q4, k4);
                mma16816(sacc[2 * np + 1], q4, k4 + 2);
            }
        }

        float rm0 = -1e30f, rm1 = -1e30f;
#pragma unroll
        for (int j = 0; j < 8; j++) {
            rm0 = fmaxf(rm0, fmaxf(sacc[j][0], sacc[j][1]));
            rm1 = fmaxf(rm1, fmaxf(sacc[j][2], sacc[j][3]));
        }
        rm0 = fmaxf(rm0, __shfl_xor_sync(0xffffffffu, rm0, 1));
        rm0 = fmaxf(rm0, __shfl_xor_sync(0xffffffffu, rm0, 2));
        rm1 = fmaxf(rm1, __shfl_xor_sync(0xffffffffu, rm1, 1));
        rm1 = fmaxf(rm1, __shfl_xor_sync(0xffffffffu, rm1, 2));
        float mn0 = fmaxf(mi0, rm0), mn1 = fmaxf(mi1, rm1);
        float al0 = expf(mi0 - mn0), al1 = expf(mi1 - mn1);
        float rs0 = 0.f, rs1 = 0.f;
#pragma unroll
        for (int j = 0; j < 8; j++) {
            sacc[j][0] = expf(sacc[j][0] - mn0); rs0 += sacc[j][0];
            sacc[j][1] = expf(sacc[j][1] - mn0); rs0 += sacc[j][1];
            sacc[j][2] = expf(sacc[j][2] - mn1); rs1 += sacc[j][2];
            sacc[j][3] = expf(sacc[j][3] - mn1); rs1 += sacc[j][3];
        }
        rs0 += __shfl_xor_sync(0xffffffffu, rs0, 1);
        rs0 += __shfl_xor_sync(0xffffffffu, rs0, 2);
        rs1 += __shfl_xor_sync(0xffffffffu, rs1, 1);
        rs1 += __shfl_xor_sync(0xffffffffu, rs1, 2);
        li0 = li0 * al0 + rs0; li1 = li1 * al1 + rs1;
        mi0 = mn0; mi1 = mn1;
#pragma unroll
        for (int t = 0; t < 8; t++) {
            oacc[t][0] *= al0; oacc[t][1] *= al0;
            oacc[t][2] *= al1; oacc[t][3] *= al1;
        }

#pragma unroll
        for (int kb = 0; kb < 4; kb++) {
            unsigned pa[4];
            pa[0] = pkh(sacc[2 * kb][0],     sacc[2 * kb][1]);
            pa[1] = pkh(sacc[2 * kb][2],     sacc[2 * kb][3]);
            pa[2] = pkh(sacc[2 * kb + 1][0], sacc[2 * kb + 1][1]);
            pa[3] = pkh(sacc[2 * kb + 1][2], sacc[2 * kb + 1][3]);
#pragma unroll
            for (int ndp = 0; ndp < 4; ndp++) {
                unsigned v4[4];
                uint32_t o = va_off + (uint32_t)(kb * 16 * F_STRIDE + ndp * 16) * 2;
                ldm_x4_t(v4, uV + o);
                mma16816(oacc[2 * ndp],     pa, v4);
                mma16816(oacc[2 * ndp + 1], pa, v4 + 2);
            }
        }
    }

    float inv0 = 1.f / li0, inv1 = 1.f / li1;
    int r = row0 + warpm * 16 + (lane >> 2);
    int cbase = h * 64 + (lane & 3) * 2;
#pragma unroll
    for (int dt = 0; dt < 8; dt++) {
        size_t idx = (size_t)(b * NS + r) * ND + cbase + dt * 8;
        *(unsigned*)(g_a16 + idx) = pkh(oacc[dt][0] * inv0, oacc[dt][1] * inv0);
        idx += (size_t)8 * ND;
        *(unsigned*)(g_a16 + idx) = pkh(oacc[dt][2] * inv1, oacc[dt][3] * inv1);
    }
}

// ---------------- reductions --------------------------------------------------
__device__ __forceinline__ void blk_reduce2(float& s, float& q)
{
    __shared__ float ss[8], sq[8];
#pragma unroll
    for (int o = 16; o; o >>= 1) {
        s += __shfl_xor_sync(0xffffffffu, s, o);
        q += __shfl_xor_sync(0xffffffffu, q, o);
    }
    int w = threadIdx.x >> 5, l = threadIdx.x & 31;
    if (l == 0) { ss[w] = s; sq[w] = q; }
    __syncthreads();
    s = (l < 8) ? ss[l] : 0.f;
    q = (l < 8) ? sq[l] : 0.f;
#pragma unroll
    for (int o = 4; o; o >>= 1) {
        s += __shfl_xor_sync(0xffffffffu, s, o);
        q += __shfl_xor_sync(0xffffffffu, q, o);
    }
    s = __shfl_sync(0xffffffffu, s, 0);
    q = __shfl_sync(0xffffffffu, q, 0);
}

// ---------------- conversions -------------------------------------------------
__global__ __launch_bounds__(256) void k_cvt_small(
    const float* __restrict__ src, const float* __restrict__ qw,
    const float* __restrict__ kw, const float* __restrict__ vw,
    const float* __restrict__ gw, const float* __restrict__ ow)
{
    size_t u = ((size_t)blockIdx.x * 256 + threadIdx.x) * 8;
    const size_t M = (size_t)ND * ND;
    if (u < 2 * M) {
        cvt8(src, g_s16, u);
    } else if (u < 5 * M) {
        size_t v = u - 2 * M;
        if (v < M) cvt8(qw, g_wqkv, v);
        else if (v < 2 * M) cvt8(kw, g_wqkv + M, v - M);
        else cvt8(vw, g_wqkv + 2 * M, v - 2 * M);
    } else if (u < 6 * M) {
        cvt8(gw, g_wg, u - 5 * M);
    } else {
        cvt8(ow, g_wo, u - 6 * M);
    }
}

// ---------------- elementwise -------------------------------------------------
__global__ __launch_bounds__(256) void k_qscale(const float* __restrict__ sw)
{
    int wid = blockIdx.x * 8 + (threadIdx.x >> 5);
    int lane = threadIdx.x & 31;
    int h = wid & (NH - 1), t = wid >> 4;
    size_t i0 = (size_t)t * ND + h * 64 + lane;
    float q0 = __half2float(g_qkv[i0]);
    float q1 = __half2float(g_qkv[i0 + 32]);
    float s = q0 * sw[h * 64 + lane] + q1 * sw[h * 64 + lane + 32];
#pragma unroll
    for (int o = 16; o; o >>= 1) s += __shfl_xor_sync(0xffffffffu, s, o);
    if (lane == 0) {
        float sig = 1.f / (1.f + expf(-s));
        int b = t >> 10, si = t & (NS - 1);
        g_scalef[(b * NH + h) * NS + si] = 0.25f * sig;
    }
}

// fused LayerNorm1 + MoE routing: one block per token
__global__ __launch_bounds__(256) void k_ln1_route(
    const float* __restrict__ g, const float* __restrict__ b,
    const float* __restrict__ gw, const float* __restrict__ gb)
{
    __shared__ float slog[NE * 8];
    size_t r = blockIdx.x;
    const float* in = g_xres + r * ND;
    float x[4];
    float s = 0.f, q = 0.f;
#pragma unroll
    for (int l = 0; l < 4; l++) {
        x[l] = in[threadIdx.x + l * 256];
        s += x[l]; q += x[l] * x[l];
    }
    blk_reduce2(s, q);
    float mean = s * (1.f / ND);
    float var = q * (1.f / ND) - mean * mean;
    float rstd = rsqrtf(var + 1e-5f);
    float part[NE];
#pragma unroll
    for (int e = 0; e < NE; e++) part[e] = 0.f;
#pragma unroll
    for (int l = 0; l < 4; l++) {
        int c = threadIdx.x + l * 256;
        float v = (x[l] - mean) * rstd * g[c] + b[c];
        g_x[r * ND + c] = v;
        g_x16[r * ND + c] = __float2half_rn(v);
#pragma unroll
        for (int e = 0; e < NE; e++) part[e] += v * gw[c * NE + e];
    }
    // warp reduce 8 partials, then cross-warp
#pragma unroll
    for (int e = 0; e < NE; e++) {
#pragma unroll
        for (int o = 16; o; o >>= 1) part[e] += __shfl_xor_sync(0xffffffffu, part[e], o);
    }
    int w = threadIdx.x >> 5, lane = threadIdx.x & 31;
    if (lane == 0) {
#pragma unroll
        for (int e = 0; e < NE; e++) slog[w * NE + e] = part[e];
    }
    __syncthreads();
    if (threadIdx.x == 0) {
        float lg[NE];
#pragma unroll
        for (int e = 0; e < NE; e++) {
            float acc = gb[e];
#pragma unroll
            for (int w2 = 0; w2 < 8; w2++) acc += slog[w2 * NE + e];
            lg[e] = acc;
        }
        int i1 = 0; float v1 = lg[0];
#pragma unroll
        for (int e = 1; e < NE; e++) if (lg[e] > v1) { v1 = lg[e]; i1 = e; }
        int i2 = -1; float v2 = -1e30f;
#pragma unroll
        for (int e = 0; e < NE; e++) if (e != i1 && lg[e] > v2) { v2 = lg[e]; i2 = e; }
        g_esel[r] = (i1 > i2) ? i1 : i2;
    }
}

__global__ __launch_bounds__(256) void k_ln_out(const float* __restrict__ g,
                                                const float* __restrict__ b,
                                                float* __restrict__ out)
{
    size_t r = blockIdx.x;
    const float* in = g_z + r * ND;
    float x[4];
    float s = 0.f, q = 0.f;
#pragma unroll
    for (int l = 0; l < 4; l++) {
        x[l] = in[threadIdx.x + l * 256];
        s += x[l]; q += x[l] * x[l];
    }
    blk_reduce2(s, q);
    float mean = s * (1.f / ND);
    float var = q * (1.f / ND) - mean * mean;
    float rstd = rsqrtf(var + 1e-5f);
#pragma unroll
    for (int l = 0; l < 4; l++) {
        int c = threadIdx.x + l * 256;
        out[r * ND + c] = (x[l] - mean) * rstd * g[c] + b[c];
    }
}

__global__ void k_scatter()
{
    __shared__ int scnt[NE], soff[NE], scur[NE];
    int tid = threadIdx.x;
    if (tid < NE) scnt[tid] = 0;
    __syncthreads();
    for (int t = tid; t < NT; t += 1024) atomicAdd(&scnt[g_esel[t]], 1);
    __syncthreads();
    if (tid == 0) {
        int r = 0;
        for (int e = 0; e < NE; e++) { soff[e] = r; r += scnt[e]; }
    }
    __syncthreads();
    if (tid < NE) { scur[tid] = soff[tid]; g_off[tid] = soff[tid]; g_cnt[tid] = scnt[tid]; }
    __syncthreads();
    for (int t = tid; t < NT; t += 1024) {
        int e = g_esel[t];
        int pos = atomicAdd(&scur[e], 1);
        g_perm[pos] = t;
        g_eid[pos] = e;
    }
}

__global__ __launch_bounds__(256) void k_lngelu(const float* __restrict__ lng,
                                                const float* __restrict__ lnb)
{
    int row = blockIdx.x;
    int e = g_eid[row];
    const float* hp = g_h + (size_t)row * NF;
    float x[16];
    float s = 0.f, q = 0.f;
#pragma unroll
    for (int l = 0; l < 16; l++) {
        x[l] = hp[threadIdx.x + l * 256];
        s += x[l]; q += x[l] * x[l];
    }
    blk_reduce2(s, q);
    float mean = s * (1.f / NF);
    float var = q * (1.f / NF) - mean * mean;
    float rstd = rsqrtf(var + 1e-5f);
    const float* g = lng + (size_t)e * NF;
    const float* b = lnb + (size_t)e * NF;
#pragma unroll
    for (int l = 0; l < 16; l++) {
        int c = threadIdx.x + l * 256;
        float hn = (x[l] - mean) * rstd * g[c] + b[c];
        float gel = 0.5f * hn * (1.f + erff(hn * 0.70710678118654752f));
        g_h16[(size_t)row * NF + c] = __float2half_rn(gel);
    }
}

// ---------------- launch ------------------------------------------------------
extern "C" void kernel_launch(void* const* d_in, const int* in_sizes, int n_in,
                              void* d_out, int out_size)
{
    (void)in_sizes; (void)n_in; (void)out_size;
    const float* src        = (const float*)d_in[0];
    const float* qw         = (const float*)d_in[1];
    const float* kw         = (const float*)d_in[2];
    const float* vw         = (const float*)d_in[3];
    const float* ow         = (const float*)d_in[4];
    const float* gate_w     = (const float*)d_in[5];
    const float* gate_b     = (const float*)d_in[6];
    const float* scale_w    = (const float*)d_in[7];
    const float* n1_g       = (const float*)d_in[8];
    const float* n1_b       = (const float*)d_in[9];
    const float* n2_g       = (const float*)d_in[10];
    const float* n2_b       = (const float*)d_in[11];
    const float* moe_gate_w = (const float*)d_in[12];
    const float* moe_gate_b = (const float*)d_in[13];
    const float* w1         = (const float*)d_in[14];
    const float* b1         = (const float*)d_in[15];
    const float* ln_g       = (const float*)d_in[16];
    const float* ln_b       = (const float*)d_in[17];
    const float* w2         = (const float*)d_in[18];
    const float* b2         = (const float*)d_in[19];
    const float* res_scale  = (const float*)d_in[20];
    float* out = (float*)d_out;

    cudaFuncSetAttribute((const void*)k_mm<0>, cudaFuncAttributeMaxDynamicSharedMemorySize, GEMM_SMEM);
    cudaFuncSetAttribute((const void*)k_mm<1>, cudaFuncAttributeMaxDynamicSharedMemorySize, GEMM_SMEM);
    cudaFuncSetAttribute((const void*)k_mm<2>, cudaFuncAttributeMaxDynamicSharedMemorySize, GEMM_SMEM);
    cudaFuncSetAttribute((const void*)k_mm<3>, cudaFuncAttributeMaxDynamicSharedMemorySize, GEMM_SMEM);
    cudaFuncSetAttribute((const void*)k_mm<4>, cudaFuncAttributeMaxDynamicSharedMemorySize, GEMM_SMEM);
    cudaFuncSetAttribute((const void*)k_flash, cudaFuncAttributeMaxDynamicSharedMemorySize, FLASH_SMEM);

    __half *s16, *qkv, *a16, *g16, *x16, *h16, *wqkv, *wg, *wo, *w116, *w216;
    float *xres, *x, *z, *hbuf;
    cudaGetSymbolAddress((void**)&s16, g_s16);
    cudaGetSymbolAddress((void**)&qkv, g_qkv);
    cudaGetSymbolAddress((void**)&a16, g_a16);
    cudaGetSymbolAddress((void**)&g16, g_g16);
    cudaGetSymbolAddress((void**)&x16, g_x16);
    cudaGetSymbolAddress((void**)&h16, g_h16);
    cudaGetSymbolAddress((void**)&wqkv, g_wqkv);
    cudaGetSymbolAddress((void**)&wg, g_wg);
    cudaGetSymbolAddress((void**)&wo, g_wo);
    cudaGetSymbolAddress((void**)&w116, g_w116);
    cudaGetSymbolAddress((void**)&w216, g_w216);
    cudaGetSymbolAddress((void**)&xres, g_xres);
    cudaGetSymbolAddress((void**)&x, g_x);
    cudaGetSymbolAddress((void**)&z, g_z);
    cudaGetSymbolAddress((void**)&hbuf, g_h);

    k_cvt_small<<<7 * 1024 * 1024 / 2048, 256>>>(src, qw, kw, vw, gate_w, ow);

    k_mm<0><<<dim3(ND / TN, NT / TM, 4), 256, GEMM_SMEM>>>(s16, wqkv,
        ND, ND, nullptr, w1, nullptr, qkv, nullptr);
    k_qscale<<<(NT * NH) / 8, 256>>>(scale_w);
    k_flash<<<dim3(NS / 64, NB * NH, 2), 128, FLASH_SMEM>>>(w2);
    k_mm<1><<<dim3(ND / TN, NT / TM), 256, GEMM_SMEM>>>(a16, wg,
        ND, ND, gate_b, nullptr, nullptr, g16, nullptr);
    k_mm<2><<<dim3(ND / TN, NT / TM), 256, GEMM_SMEM>>>(g16, wo,
        ND, ND, nullptr, src, nullptr, nullptr, xres);
    k_ln1_route<<<NT, 256>>>(n1_g, n1_b, moe_gate_w, moe_gate_b);
    k_scatter<<<1, 1024>>>();
    k_mm<3><<<dim3(NF / TN, NT / TM, NE), 256, GEMM_SMEM>>>(x16, w116,
        ND, NF, b1, nullptr, nullptr, nullptr, hbuf);
    k_lngelu<<<NT, 256>>>(ln_g, ln_b);
    k_mm<4><<<dim3(ND / TN, NT / TM, NE), 256, GEMM_SMEM>>>(h16, w216,
        NF, ND, b2, x, res_scale, nullptr, z);
    k_ln_out<<<NT, 256>>>(n2_g, n2_b, out);
}

// round 13
// speedup vs baseline: 1.7004x; 1.1682x over previous
#include <cuda_runtime.h>
#include <cuda_fp16.h>
#include <math.h>
#include <stdint.h>

#define NB 2
#define NS 1024
#define ND 1024
#define NH 16
#define NE 8
#define NF 4096
#define NT 2048

#define TM 128
#define TN 128
#define KC 32
#define A_STRIDE 40    // fp16 elems per A smem row (80B)
#define B_STRIDE 136   // fp16 elems per B smem row (272B)

// 4-stage fp16 pipeline
#define ST_A 0
#define ST_B 10240
#define STAGE_BYTES 18944
#define NST1 4
#define GEMM_SMEM (NST1 * STAGE_BYTES)

#define F_STRIDE 72    // flash smem row stride (144B)
#define F_Q 0
#define F_K 9216
#define F_V 18432
#define FLASH_SMEM 27648

#define WELEMS ((size_t)NE * ND * NF)   // 33.55M elems per ffn weight

// ---------------- scratch ----------------------------------------------------
__device__ __half g_s16[NT * ND];
__device__ __half g_qkv[3 * NT * ND];
__device__ __half g_a16[NT * ND];
__device__ __half g_g16[NT * ND];
__device__ __half g_x16[NT * ND];
__device__ __half g_h16[(size_t)NT * NF];
__device__ __half g_wqkv[3 * ND * ND];
__device__ __half g_wg[ND * ND];
__device__ __half g_wo[ND * ND];
__device__ __half g_w116[WELEMS];
__device__ __half g_w216[WELEMS];
__device__ float g_scalef[NB * NH * NS];
__device__ float g_xres[NT * ND];
__device__ float g_xres2[NT * ND];
__device__ float g_x[NT * ND];
__device__ float g_z[NT * ND];
__device__ float g_z2[NT * ND];
__device__ float g_h[(size_t)NT * NF];
__device__ int g_esel[NT];
__device__ int g_perm[NT];
__device__ int g_eid[NT];
__device__ int g_off[NE];
__device__ int g_cnt[NE];

// ---------------- helpers ----------------------------------------------------
__device__ __forceinline__ uint32_t s2u(const void* p) {
    uint32_t a;
    asm("{ .reg .u64 t; cvta.to.shared.u64 t, %1; cvt.u32.u64 %0, t; }" : "=r"(a) : "l"(p));
    return a;
}
__device__ __forceinline__ unsigned pkh(float a, float b) {
    __half2 hh = __floats2half2_rn(a, b);
    return *reinterpret_cast<unsigned*>(&hh);
}
__device__ __forceinline__ void ldm_x4(unsigned* r, uint32_t addr) {
    asm volatile("ldmatrix.sync.aligned.m8n8.x4.shared.b16 {%0,%1,%2,%3}, [%4];"
        : "=r"(r[0]), "=r"(r[1]), "=r"(r[2]), "=r"(r[3]) : "r"(addr));
}
__device__ __forceinline__ void ldm_x4_t(unsigned* r, uint32_t addr) {
    asm volatile("ldmatrix.sync.aligned.m8n8.x4.trans.shared.b16 {%0,%1,%2,%3}, [%4];"
        : "=r"(r[0]), "=r"(r[1]), "=r"(r[2]), "=r"(r[3]) : "r"(addr));
}
__device__ __forceinline__ void mma16816(float* c, const unsigned* a, const unsigned* b) {
    asm volatile(
        "mma.sync.aligned.m16n8k16.row.col.f32.f16.f16.f32 "
        "{%0,%1,%2,%3}, {%4,%5,%6,%7}, {%8,%9}, {%0,%1,%2,%3};"
        : "+f"(c[0]), "+f"(c[1]), "+f"(c[2]), "+f"(c[3])
        : "r"(a[0]), "r"(a[1]), "r"(a[2]), "r"(a[3]), "r"(b[0]), "r"(b[1]));
}
__device__ __forceinline__ void cpa(uint32_t d, const void* s, int szvalid) {
    asm volatile("cp.async.cg.shared.global [%0], [%1], 16, %2;"
        :: "r"(d), "l"(__cvta_generic_to_global(s)), "r"(szvalid));
}

__device__ __forceinline__ void cvt8(const float* __restrict__ in, __half* __restrict__ o,
                                     size_t i)
{
    float4 a = *(const float4*)(in + i);
    float4 b = *(const float4*)(in + i + 4);
    unsigned h[4];
    h[0] = pkh(a.x, a.y); h[1] = pkh(a.z, a.w);
    h[2] = pkh(b.x, b.y); h[3] = pkh(b.z, b.w);
    *(uint4*)(o + i) = *(uint4*)h;
}

// ---------------- pipelined mma.sync fp16 GEMM (4-stage, R10 schedule) --------
// K = per-CTA loop K; lda = A row stride (full K dim); ldB = B row stride.
// OP: 0 merged QKV (z=3 plane converts w1) | 1 gate | 2 ow split-K (+src, z=kh)
//     3 ffn1 gather +b1 | 4 ffn2 split-K (z = kh*8 + e)
template <int OP>
__global__ void __launch_bounds__(256, 2) k_mm(
    const __half* __restrict__ Ah, const __half* __restrict__ B16,
    int K, int lda, int ldB,
    const float* __restrict__ bias, const float* __restrict__ extra,
    const float* __restrict__ extra2,
    __half* __restrict__ Oh, float* __restrict__ Of)
{
    if (OP == 0 && blockIdx.z == 3) {
        size_t base = (((size_t)blockIdx.y * 8 + blockIdx.x) * 256 + threadIdx.x) * 8;
        size_t stride = (size_t)128 * 256 * 8;
        for (size_t u = base; u < WELEMS; u += stride) cvt8(extra, g_w116, u);
        return;
    }

    extern __shared__ __align__(16) char sm[];
    __shared__ int rloc[TM];

    const int tid = threadIdx.x;
    const int lane = tid & 31, wid = tid >> 5;
    const int warp_m = wid >> 2, warp_n = wid & 3;
    const int row0 = blockIdx.y * TM, col0 = blockIdx.x * TN;
    int e = 0, kh = 0;
    if (OP == 0) e = blockIdx.z;
    if (OP == 2) kh = blockIdx.z;
    if (OP == 3) e = blockIdx.z;
    if (OP == 4) { e = blockIdx.z & 7; kh = blockIdx.z >> 3; }
    int cnt = 0, off = 0;
    if (OP == 0) {
        B16 += (size_t)e * ND * ND;
        Oh += (size_t)e * NT * ND;
    }
    if (OP == 3 || OP == 4) {
        cnt = g_cnt[e]; off = g_off[e];
        if (row0 >= cnt) return;
        B16 += (size_t)e * lda * ldB;
    }
    const int koff = kh * K;
    B16 += (size_t)koff * ldB;
    if (OP == 3) {
        if (tid < TM) {
            int gr = row0 + tid;
            rloc[tid] = (gr < cnt) ? g_perm[off + gr] : -1;
        }
        __syncthreads();
    }

    const int am = tid >> 1, ahalf = tid & 1;
    int arow;
    if (OP == 3) arow = rloc[am];
    else if (OP == 4) arow = min(off + row0 + am, NT - 1);
    else arow = row0 + am;
    const int apred = (arow >= 0) ? 16 : 0;
    const int arows = (arow >= 0) ? arow : 0;
    const char* gA = (const char*)(Ah + (size_t)arows * lda + koff + ahalf * 16);
    const int bk = tid >> 3, bseg = tid & 7;
    const char* gB16 = (const char*)(B16 + (size_t)bk * ldB + col0 + bseg * 16);

    const uint32_t ub = s2u(sm);
    const uint32_t aDst = ub + ST_A + am * 80 + ahalf * 32;
    const uint32_t bDst = ub + ST_B + bk * 272 + bseg * 32;

    auto issue = [&](int stage, int c) {
        uint32_t sb = stage * STAGE_BYTES;
        size_t ao = (size_t)c * KC * 2;
        size_t bo = (size_t)c * KC * ldB * 2;
        cpa(aDst + sb,      gA + ao,      apred);
        cpa(aDst + sb + 16, gA + ao + 16, apred);
        cpa(bDst + sb,      gB16 + bo,      16);
        cpa(bDst + sb + 16, gB16 + bo + 16, 16);
        asm volatile("cp.async.commit_group;");
    };

    float acc[16][4];
#pragma unroll
    for (int t = 0; t < 16; t++)
#pragma unroll
        for (int i = 0; i < 4; i++) acc[t][i] = 0.f;

    const int nch = K / KC;
#pragma unroll
    for (int s = 0; s < NST1; s++) issue(s, s);

    for (int c = 0; c < nch; c++) {
        asm volatile("cp.async.wait_group %0;" :: "n"(NST1 - 1));
        __syncthreads();
        uint32_t sb = ub + (c % NST1) * STAGE_BYTES;
        uint32_t uA_ = sb + ST_A;
        uint32_t uB_ = sb + ST_B;
#pragma unroll
        for (int ks = 0; ks < 2; ks++) {
            unsigned b_[2][4];
#pragma unroll
            for (int nt = 0; nt < 2; nt++) {
                int krow = ks * 16 + (lane & 7) + ((lane >> 3) & 1) * 8;
                int ncol = warp_n * 32 + nt * 16 + (lane >> 4) * 8;
                uint32_t o = (uint32_t)(krow * B_STRIDE + ncol) * 2;
                ldm_x4_t(b_[nt], uB_ + o);
            }
#pragma unroll
            for (int mt = 0; mt < 4; mt++) {
                unsigned a_[4];
                int mrow = warp_m * 64 + mt * 16 + (lane & 15);
                int kcol = ks * 16 + (lane >> 4) * 8;
                uint32_t o = (uint32_t)(mrow * A_STRIDE + kcol) * 2;
                ldm_x4(a_, uA_ + o);
#pragma unroll
                for (int nt = 0; nt < 2; nt++)
#pragma unroll
                    for (int j = 0; j < 2; j++)
                        mma16816(acc[mt * 4 + nt * 2 + j], a_, b_[nt] + j * 2);
            }
        }
        __syncthreads();
        if (c + NST1 < nch) issue(c % NST1, c + NST1);
        else asm volatile("cp.async.commit_group;");
    }

    // ---- epilogue ----
    float rs = 0.f;
    if (OP == 4) rs = extra2[e];
#pragma unroll
    for (int mt = 0; mt < 4; mt++)
#pragma unroll
        for (int nt = 0; nt < 2; nt++)
#pragma unroll
            for (int j = 0; j < 2; j++) {
                float* cc = acc[mt * 4 + nt * 2 + j];
                int lcol = warp_n * 32 + nt * 16 + j * 8 + (lane & 3) * 2;
                int gcol = col0 + lcol;
#pragma unroll
                for (int half = 0; half < 2; half++) {
                    int lrow = warp_m * 64 + mt * 16 + (lane >> 2) + half * 8;
                    int gr = row0 + lrow;
                    float v0 = cc[half * 2], v1 = cc[half * 2 + 1];
                    if (OP == 0) {
                        size_t base = (size_t)gr * ND + gcol;
                        *(unsigned*)(Oh + base) = pkh(v0, v1);
                    } else if (OP == 1) {
                        size_t base = (size_t)gr * ND + gcol;
                        float g0 = 1.f / (1.f + expf(-(v0 + bias[gcol])));
                        float g1 = 1.f / (1.f + expf(-(v1 + bias[gcol + 1])));
                        float a0 = __half2float(Ah[base]);
                        float a1 = __half2float(Ah[base + 1]);
                        *(unsigned*)(Oh + base) = pkh(a0 * g0, a1 * g1);
                    } else if (OP == 2) {
                        size_t base = (size_t)gr * ND + gcol;
                        float2 o2;
                        if (kh == 0) {
                            o2.x = extra[base] + v0;
                            o2.y = extra[base + 1] + v1;
                            *(float2*)(Of + base) = o2;
                        } else {
                            o2.x = v0; o2.y = v1;
                            *(float2*)(g_xres2 + base) = o2;
                        }
                    } else if (OP == 3) {
                        if (gr < cnt) {
                            size_t base = (size_t)(off + gr) * NF + gcol;
                            float2 o2;
                            o2.x = v0 + bias[e * NF + gcol];
                            o2.y = v1 + bias[e * NF + gcol + 1];
                            *(float2*)(Of + base) = o2;
                        }
                    } else if (OP == 4) {
                        if (gr < cnt) {
                            int t = g_perm[off + gr];
                            size_t bx = (size_t)t * ND + gcol;
                            float2 o2;
                            if (kh == 0) {
                                o2.x = 2.f * extra[bx] + rs * (v0 + bias[e * ND + gcol]);
                                o2.y = 2.f * extra[bx + 1] + rs * (v1 + bias[e * ND + gcol + 1]);
                                *(float2*)(Of + bx) = o2;
                            } else {
                                o2.x = rs * v0; o2.y = rs * v1;
                                *(float2*)(g_z2 + bx) = o2;
                            }
                        }
                    }
                }
            }
}

// ---------------- mma.sync flash attention (fp16, R10 plain loads) ------------
// z=0 plane: flash attention.  z=1 plane: stream-convert w2 fp32 -> fp16.
__global__ void __launch_bounds__(128, 4) k_flash(const float* __restrict__ w2src)
{
    if (blockIdx.z == 1) {
        size_t cid = (size_t)blockIdx.y * 16 + blockIdx.x;  // 512 CTAs
        size_t base = (cid * 128 + threadIdx.x) * 8;
        size_t stride = (size_t)512 * 128 * 8;
        for (size_t u = base; u < WELEMS; u += stride) cvt8(w2src, g_w216, u);
        return;
    }

    extern __shared__ __align__(16) char fsm[];
    const int tid = threadIdx.x, lane = tid & 31, warpm = tid >> 5;
    const int bh = blockIdx.y, b = bh >> 4, h = bh & 15;
    const int row0 = blockIdx.x * 64;

    const __half* Qg = g_qkv;
    const __half* Kg = g_qkv + (size_t)NT * ND;
    const __half* Vg = g_qkv + (size_t)2 * NT * ND;

    {
        int m = tid >> 1, half = tid & 1;
        float sc = g_scalef[bh * NS + row0 + m];
        const __half* src_ = Qg + (size_t)(b * NS + row0 + m) * ND + h * 64 + half * 32;
        char* dq = fsm + F_Q + m * 144 + half * 64;
#pragma unroll
        for (int i = 0; i < 4; i++) {
            __half qb[8];
            *(uint4*)qb = *(const uint4*)(src_ + i * 8);
            unsigned o4[4];
#pragma unroll
            for (int j = 0; j < 4; j++)
                o4[j] = pkh(__half2float(qb[2 * j]) * sc, __half2float(qb[2 * j + 1]) * sc);
            *(uint4*)(dq + i * 16) = *(uint4*)o4;
        }
    }

    const uint32_t ubase = s2u(fsm);
    const uint32_t uQ = ubase + F_Q, uK = ubase + F_K, uV = ubase + F_V;

    const uint32_t qa_off = ((warpm * 16 + (lane & 15)) * F_STRIDE + ((lane >> 4) & 1) * 8) * 2;
    const uint32_t ka_off = (((lane & 7) + ((lane >> 4) << 3)) * F_STRIDE + ((lane >> 3) & 1) * 8) * 2;
    const uint32_t va_off = (((lane & 7) + ((lane >> 3) & 1) * 8) * F_STRIDE + ((lane >> 4) & 1) * 8) * 2;

    float oacc[8][4];
#pragma unroll
    for (int t = 0; t < 8; t++)
#pragma unroll
        for (int i = 0; i < 4; i++) oacc[t][i] = 0.f;
    float mi0 = -1e30f, mi1 = -1e30f, li0 = 0.f, li1 = 0.f;

    for (int jt = 0; jt < NS / 64; jt++) {
        __syncthreads();
        {
            int m = tid >> 1, half = tid & 1;
            size_t gsrc = (size_t)(b * NS + jt * 64 + m) * ND + h * 64 + half * 32;
            char* dk = fsm + F_K + m * 144 + half * 64;
            char* dv = fsm + F_V + m * 144 + half * 64;
#pragma unroll
            for (int i = 0; i < 4; i++) {
                *(uint4*)(dk + i * 16) = *(const uint4*)((const char*)(Kg + gsrc) + i * 16);
                *(uint4*)(dv + i * 16) = *(const uint4*)((const char*)(Vg + gsrc) + i * 16);
            }
        }
        __syncthreads();

        float sacc[8][4];
#pragma unroll
        for (int t = 0; t < 8; t++)
#pragma unroll
            for (int i = 0; i < 4; i++) sacc[t][i] = 0.f;
#pragma unroll
        for (int ks = 0; ks < 4; ks++) {
            unsigned q4[4];
            ldm_x4(q4, uQ + qa_off + ks * 32);
#pragma unroll
            for (int np = 0; np < 4; np++) {
                unsigned k4[4];
                uint32_t o = ka_off + (uint32_t)(np * 16 * F_STRIDE + ks * 16) * 2;
                ldm_x4(k4, uK + o);
                mma16816(sacc[2 * np],     q4, k4);
                mma16816(sacc[2 * np + 1], q4, k4 + 2);
            }
        }

        float rm0 = -1e30f, rm1 = -1e30f;
#pragma unroll
        for (int j = 0; j < 8; j++) {
            rm0 = fmaxf(rm0, fmaxf(sacc[j][0], sacc[j][1]));
            rm1 = fmaxf(rm1, fmaxf(sacc[j][2], sacc[j][3]));
        }
        rm0 = fmaxf(rm0, __shfl_xor_sync(0xffffffffu, rm0, 1));
        rm0 = fmaxf(rm0, __shfl_xor_sync(0xffffffffu, rm0, 2));
        rm1 = fmaxf(rm1, __shfl_xor_sync(0xffffffffu, rm1, 1));
        rm1 = fmaxf(rm1, __shfl_xor_sync(0xffffffffu, rm1, 2));
        float mn0 = fmaxf(mi0, rm0), mn1 = fmaxf(mi1, rm1);
        float al0 = expf(mi0 - mn0), al1 = expf(mi1 - mn1);
        float rs0 = 0.f, rs1 = 0.f;
#pragma unroll
        for (int j = 0; j < 8; j++) {
            sacc[j][0] = expf(sacc[j][0] - mn0); rs0 += sacc[j][0];
            sacc[j][1] = expf(sacc[j][1] - mn0); rs0 += sacc[j][1];
            sacc[j][2] = expf(sacc[j][2] - mn1); rs1 += sacc[j][2];
            sacc[j][3] = expf(sacc[j][3] - mn1); rs1 += sacc[j][3];
        }
        rs0 += __shfl_xor_sync(0xffffffffu, rs0, 1);
        rs0 += __shfl_xor_sync(0xffffffffu, rs0, 2);
        rs1 += __shfl_xor_sync(0xffffffffu, rs1, 1);
        rs1 += __shfl_xor_sync(0xffffffffu, rs1, 2);
        li0 = li0 * al0 + rs0; li1 = li1 * al1 + rs1;
        mi0 = mn0; mi1 = mn1;
#pragma unroll
        for (int t = 0; t < 8; t++) {
            oacc[t][0] *= al0; oacc[t][1] *= al0;
            oacc[t][2] *= al1; oacc[t][3] *= al1;
        }

#pragma unroll
        for (int kb = 0; kb < 4; kb++) {
            unsigned pa[4];
            pa[0] = pkh(sacc[2 * kb][0],     sacc[2 * kb][1]);
            pa[1] = pkh(sacc[2 * kb][2],     sacc[2 * kb][3]);
            pa[2] = pkh(sacc[2 * kb + 1][0], sacc[2 * kb + 1][1]);
            pa[3] = pkh(sacc[2 * kb + 1][2], sacc[2 * kb + 1][3]);
#pragma unroll
            for (int ndp = 0; ndp < 4; ndp++) {
                unsigned v4[4];
                uint32_t o = va_off + (uint32_t)(kb * 16 * F_STRIDE + ndp * 16) * 2;
                ldm_x4_t(v4, uV + o);
                mma16816(oacc[2 * ndp],     pa, v4);
                mma16816(oacc[2 * ndp + 1], pa, v4 + 2);
            }
        }
    }

    float inv0 = 1.f / li0, inv1 = 1.f / li1;
    int r = row0 + warpm * 16 + (lane >> 2);
    int cbase = h * 64 + (lane & 3) * 2;
#pragma unroll
    for (int dt = 0; dt < 8; dt++) {
        size_t idx = (size_t)(b * NS + r) * ND + cbase + dt * 8;
        *(unsigned*)(g_a16 + idx) = pkh(oacc[dt][0] * inv0, oacc[dt][1] * inv0);
        idx += (size_t)8 * ND;
        *(unsigned*)(g_a16 + idx) = pkh(oacc[dt][2] * inv1, oacc[dt][3] * inv1);
    }
}

// ---------------- reductions --------------------------------------------------
__device__ __forceinline__ void blk_reduce2(float& s, float& q)
{
    __shared__ float ss[8], sq[8];
#pragma unroll
    for (int o = 16; o; o >>= 1) {
        s += __shfl_xor_sync(0xffffffffu, s, o);
        q += __shfl_xor_sync(0xffffffffu, q, o);
    }
    int w = threadIdx.x >> 5, l = threadIdx.x & 31;
    if (l == 0) { ss[w] = s; sq[w] = q; }
    __syncthreads();
    s = (l < 8) ? ss[l] : 0.f;
    q = (l < 8) ? sq[l] : 0.f;
#pragma unroll
    for (int o = 4; o; o >>= 1) {
        s += __shfl_xor_sync(0xffffffffu, s, o);
        q += __shfl_xor_sync(0xffffffffu, q, o);
    }
    s = __shfl_sync(0xffffffffu, s, 0);
    q = __shfl_sync(0xffffffffu, q, 0);
}

// ---------------- conversions -------------------------------------------------
__global__ __launch_bounds__(256) void k_cvt_small(
    const float* __restrict__ src, const float* __restrict__ qw,
    const float* __restrict__ kw, const float* __restrict__ vw,
    const float* __restrict__ gw, const float* __restrict__ ow)
{
    size_t u = ((size_t)blockIdx.x * 256 + threadIdx.x) * 8;
    const size_t M = (size_t)ND * ND;
    if (u < 2 * M) {
        cvt8(src, g_s16, u);
    } else if (u < 5 * M) {
        size_t v = u - 2 * M;
        if (v < M) cvt8(qw, g_wqkv, v);
        else if (v < 2 * M) cvt8(kw, g_wqkv + M, v - M);
        else cvt8(vw, g_wqkv + 2 * M, v - 2 * M);
    } else if (u < 6 * M) {
        cvt8(gw, g_wg, u - 5 * M);
    } else {
        cvt8(ow, g_wo, u - 6 * M);
    }
}

// ---------------- elementwise -------------------------------------------------
__global__ __launch_bounds__(256) void k_qscale(const float* __restrict__ sw)
{
    int wid = blockIdx.x * 8 + (threadIdx.x >> 5);
    int lane = threadIdx.x & 31;
    int h = wid & (NH - 1), t = wid >> 4;
    size_t i0 = (size_t)t * ND + h * 64 + lane;
    float q0 = __half2float(g_qkv[i0]);
    float q1 = __half2float(g_qkv[i0 + 32]);
    float s = q0 * sw[h * 64 + lane] + q1 * sw[h * 64 + lane + 32];
#pragma unroll
    for (int o = 16; o; o >>= 1) s += __shfl_xor_sync(0xffffffffu, s, o);
    if (lane == 0) {
        float sig = 1.f / (1.f + expf(-s));
        int b = t >> 10, si = t & (NS - 1);
        g_scalef[(b * NH + h) * NS + si] = 0.25f * sig;
    }
}

// fused LayerNorm1 + MoE routing (reads split-K partials)
__global__ __launch_bounds__(256) void k_ln1_route(
    const float* __restrict__ g, const float* __restrict__ b,
    const float* __restrict__ gw, const float* __restrict__ gb)
{
    __shared__ float slog[NE * 8];
    size_t r = blockIdx.x;
    const float* in = g_xres + r * ND;
    const float* in2 = g_xres2 + r * ND;
    float x[4];
    float s = 0.f, q = 0.f;
#pragma unroll
    for (int l = 0; l < 4; l++) {
        int c = threadIdx.x + l * 256;
        x[l] = in[c] + in2[c];
        s += x[l]; q += x[l] * x[l];
    }
    blk_reduce2(s, q);
    float mean = s * (1.f / ND);
    float var = q * (1.f / ND) - mean * mean;
    float rstd = rsqrtf(var + 1e-5f);
    float part[NE];
#pragma unroll
    for (int e = 0; e < NE; e++) part[e] = 0.f;
#pragma unroll
    for (int l = 0; l < 4; l++) {
        int c = threadIdx.x + l * 256;
        float v = (x[l] - mean) * rstd * g[c] + b[c];
        g_x[r * ND + c] = v;
        g_x16[r * ND + c] = __float2half_rn(v);
#pragma unroll
        for (int e = 0; e < NE; e++) part[e] += v * gw[c * NE + e];
    }
#pragma unroll
    for (int e = 0; e < NE; e++) {
#pragma unroll
        for (int o = 16; o; o >>= 1) part[e] += __shfl_xor_sync(0xffffffffu, part[e], o);
    }
    int w = threadIdx.x >> 5, lane = threadIdx.x & 31;
    if (lane == 0) {
#pragma unroll
        for (int e = 0; e < NE; e++) slog[w * NE + e] = part[e];
    }
    __syncthreads();
    if (threadIdx.x == 0) {
        float lg[NE];
#pragma unroll
        for (int e = 0; e < NE; e++) {
            float acc = gb[e];
#pragma unroll
            for (int w2 = 0; w2 < 8; w2++) acc += slog[w2 * NE + e];
            lg[e] = acc;
        }
        int i1 = 0; float v1 = lg[0];
#pragma unroll
        for (int e = 1; e < NE; e++) if (lg[e] > v1) { v1 = lg[e]; i1 = e; }
        int i2 = -1; float v2 = -1e30f;
#pragma unroll
        for (int e = 0; e < NE; e++) if (e != i1 && lg[e] > v2) { v2 = lg[e]; i2 = e; }
        g_esel[r] = (i1 > i2) ? i1 : i2;
    }
}

__global__ __launch_bounds__(256) void k_ln_out(const float* __restrict__ g,
                                                const float* __restrict__ b,
                                                float* __restrict__ out)
{
    size_t r = blockIdx.x;
    const float* in = g_z + r * ND;
    const float* in2 = g_z2 + r * ND;
    float x[4];
    float s = 0.f, q = 0.f;
#pragma unroll
    for (int l = 0; l < 4; l++) {
        int c = threadIdx.x + l * 256;
        x[l] = in[c] + in2[c];
        s += x[l]; q += x[l] * x[l];
    }
    blk_reduce2(s, q);
    float mean = s * (1.f / ND);
    float var = q * (1.f / ND) - mean * mean;
    float rstd = rsqrtf(var + 1e-5f);
#pragma unroll
    for (int l = 0; l < 4; l++) {
        int c = threadIdx.x + l * 256;
        out[r * ND + c] = (x[l] - mean) * rstd * g[c] + b[c];
    }
}

__global__ void k_scatter()
{
    __shared__ int scnt[NE], soff[NE], scur[NE];
    int tid = threadIdx.x;
    if (tid < NE) scnt[tid] = 0;
    __syncthreads();
    for (int t = tid; t < NT; t += 1024) atomicAdd(&scnt[g_esel[t]], 1);
    __syncthreads();
    if (tid == 0) {
        int r = 0;
        for (int e = 0; e < NE; e++) { soff[e] = r; r += scnt[e]; }
    }
    __syncthreads();
    if (tid < NE) { scur[tid] = soff[tid]; g_off[tid] = soff[tid]; g_cnt[tid] = scnt[tid]; }
    __syncthreads();
    for (int t = tid; t < NT; t += 1024) {
        int e = g_esel[t];
        int pos = atomicAdd(&scur[e], 1);
        g_perm[pos] = t;
        g_eid[pos] = e;
    }
}

__global__ __launch_bounds__(256) void k_lngelu(const float* __restrict__ lng,
                                                const float* __restrict__ lnb)
{
    int row = blockIdx.x;
    int e = g_eid[row];
    const float* hp = g_h + (size_t)row * NF;
    float x[16];
    float s = 0.f, q = 0.f;
#pragma unroll
    for (int l = 0; l < 16; l++) {
        x[l] = hp[threadIdx.x + l * 256];
        s += x[l]; q += x[l] * x[l];
    }
    blk_reduce2(s, q);
    float mean = s * (1.f / NF);
    float var = q * (1.f / NF) - mean * mean;
    float rstd = rsqrtf(var + 1e-5f);
    const float* g = lng + (size_t)e * NF;
    const float* b = lnb + (size_t)e * NF;
#pragma unroll
    for (int l = 0; l < 16; l++) {
        int c = threadIdx.x + l * 256;
        float hn = (x[l] - mean) * rstd * g[c] + b[c];
        float gel = 0.5f * hn * (1.f + erff(hn * 0.70710678118654752f));
        g_h16[(size_t)row * NF + c] = __float2half_rn(gel);
    }
}

// ---------------- launch ------------------------------------------------------
extern "C" void kernel_launch(void* const* d_in, const int* in_sizes, int n_in,
                              void* d_out, int out_size)
{
    (void)in_sizes; (void)n_in; (void)out_size;
    const float* src        = (const float*)d_in[0];
    const float* qw         = (const float*)d_in[1];
    const float* kw         = (const float*)d_in[2];
    const float* vw         = (const float*)d_in[3];
    const float* ow         = (const float*)d_in[4];
    const float* gate_w     = (const float*)d_in[5];
    const float* gate_b     = (const float*)d_in[6];
    const float* scale_w    = (const float*)d_in[7];
    const float* n1_g       = (const float*)d_in[8];
    const float* n1_b       = (const float*)d_in[9];
    const float* n2_g       = (const float*)d_in[10];
    const float* n2_b       = (const float*)d_in[11];
    const float* moe_gate_w = (const float*)d_in[12];
    const float* moe_gate_b = (const float*)d_in[13];
    const float* w1         = (const float*)d_in[14];
    const float* b1         = (const float*)d_in[15];
    const float* ln_g       = (const float*)d_in[16];
    const float* ln_b       = (const float*)d_in[17];
    const float* w2         = (const float*)d_in[18];
    const float* b2         = (const float*)d_in[19];
    const float* res_scale  = (const float*)d_in[20];
    float* out = (float*)d_out;

    cudaFuncSetAttribute((const void*)k_mm<0>, cudaFuncAttributeMaxDynamicSharedMemorySize, GEMM_SMEM);
    cudaFuncSetAttribute((const void*)k_mm<1>, cudaFuncAttributeMaxDynamicSharedMemorySize, GEMM_SMEM);
    cudaFuncSetAttribute((const void*)k_mm<2>, cudaFuncAttributeMaxDynamicSharedMemorySize, GEMM_SMEM);
    cudaFuncSetAttribute((const void*)k_mm<3>, cudaFuncAttributeMaxDynamicSharedMemorySize, GEMM_SMEM);
    cudaFuncSetAttribute((const void*)k_mm<4>, cudaFuncAttributeMaxDynamicSharedMemorySize, GEMM_SMEM);
    cudaFuncSetAttribute((const void*)k_flash, cudaFuncAttributeMaxDynamicSharedMemorySize, FLASH_SMEM);

    __half *s16, *qkv, *a16, *g16, *x16, *h16, *wqkv, *wg, *wo, *w116, *w216;
    float *xres, *x, *z, *hbuf;
    cudaGetSymbolAddress((void**)&s16, g_s16);
    cudaGetSymbolAddress((void**)&qkv, g_qkv);
    cudaGetSymbolAddress((void**)&a16, g_a16);
    cudaGetSymbolAddress((void**)&g16, g_g16);
    cudaGetSymbolAddress((void**)&x16, g_x16);
    cudaGetSymbolAddress((void**)&h16, g_h16);
    cudaGetSymbolAddress((void**)&wqkv, g_wqkv);
    cudaGetSymbolAddress((void**)&wg, g_wg);
    cudaGetSymbolAddress((void**)&wo, g_wo);
    cudaGetSymbolAddress((void**)&w116, g_w116);
    cudaGetSymbolAddress((void**)&w216, g_w216);
    cudaGetSymbolAddress((void**)&xres, g_xres);
    cudaGetSymbolAddress((void**)&x, g_x);
    cudaGetSymbolAddress((void**)&z, g_z);
    cudaGetSymbolAddress((void**)&hbuf, g_h);

    k_cvt_small<<<7 * 1024 * 1024 / 2048, 256>>>(src, qw, kw, vw, gate_w, ow);

    k_mm<0><<<dim3(ND / TN, NT / TM, 4), 256, GEMM_SMEM>>>(s16, wqkv,
        ND, ND, ND, nullptr, w1, nullptr, qkv, nullptr);
    k_qscale<<<(NT * NH) / 8, 256>>>(scale_w);
    k_flash<<<dim3(NS / 64, NB * NH, 2), 128, FLASH_SMEM>>>(w2);
    k_mm<1><<<dim3(ND / TN, NT / TM), 256, GEMM_SMEM>>>(a16, wg,
        ND, ND, ND, gate_b, nullptr, nullptr, g16, nullptr);
    k_mm<2><<<dim3(ND / TN, NT / TM, 2), 256, GEMM_SMEM>>>(g16, wo,
        ND / 2, ND, ND, nullptr, src, nullptr, nullptr, xres);
    k_ln1_route<<<NT, 256>>>(n1_g, n1_b, moe_gate_w, moe_gate_b);
    k_scatter<<<1, 1024>>>();
    k_mm<3><<<dim3(NF / TN, NT / TM, NE), 256, GEMM_SMEM>>>(x16, w116,
        ND, ND, NF, b1, nullptr, nullptr, nullptr, hbuf);
    k_lngelu<<<NT, 256>>>(ln_g, ln_b);
    k_mm<4><<<dim3(ND / TN, NT / TM, 2 * NE), 256, GEMM_SMEM>>>(h16, w216,
        NF / 2, NF, ND, b2, x, res_scale, nullptr, z);
    k_ln_out<<<NT, 256>>>(n2_g, n2_b, out);
}

// round 14
// speedup vs baseline: 1.7303x; 1.0175x over previous
#include <cuda_runtime.h>
#include <cuda_fp16.h>
#include <math.h>
#include <stdint.h>

#define NB 2
#define NS 1024
#define ND 1024
#define NH 16
#define NE 8
#define NF 4096
#define NT 2048

#define TM 128
#define TN 128
#define KC 32
#define A_STRIDE 40    // fp16 elems per A smem row (80B)
#define B_STRIDE 136   // fp16 elems per B smem row (272B)

// 4-stage fp16 pipeline
#define ST_A 0
#define ST_B 10240
#define STAGE_BYTES 18944
#define NST1 4
#define GEMM_SMEM (NST1 * STAGE_BYTES)

#define F_STRIDE 72    // flash smem row stride (144B)
#define F_Q 0
#define F_K 9216
#define F_V 18432
#define FLASH_SMEM 27648

#define WELEMS ((size_t)NE * ND * NF)   // 33.55M elems per ffn weight

// ---------------- scratch ----------------------------------------------------
__device__ __half g_s16[NT * ND];
__device__ __half g_qkv[3 * NT * ND];
__device__ __half g_a16[NT * ND];
__device__ __half g_g16[NT * ND];
__device__ __half g_x16[NT * ND];
__device__ __half g_h16[(size_t)NT * NF];
__device__ __half g_wqkv[3 * ND * ND];
__device__ __half g_wg[ND * ND];
__device__ __half g_wo[ND * ND];
__device__ __half g_w116[WELEMS];
__device__ __half g_w216[WELEMS];
__device__ float g_xres[NT * ND];
__device__ float g_xres2[NT * ND];
__device__ float g_x[NT * ND];
__device__ float g_z[NT * ND];
__device__ float g_z2[NT * ND];
__device__ float g_h[(size_t)NT * NF];
__device__ int g_esel[NT];
__device__ int g_perm[NT];
__device__ int g_eid[NT];
__device__ int g_off[NE];
__device__ int g_cnt[NE];

// ---------------- helpers ----------------------------------------------------
__device__ __forceinline__ uint32_t s2u(const void* p) {
    uint32_t a;
    asm("{ .reg .u64 t; cvta.to.shared.u64 t, %1; cvt.u32.u64 %0, t; }" : "=r"(a) : "l"(p));
    return a;
}
__device__ __forceinline__ unsigned pkh(float a, float b) {
    __half2 hh = __floats2half2_rn(a, b);
    return *reinterpret_cast<unsigned*>(&hh);
}
__device__ __forceinline__ void ldm_x4(unsigned* r, uint32_t addr) {
    asm volatile("ldmatrix.sync.aligned.m8n8.x4.shared.b16 {%0,%1,%2,%3}, [%4];"
        : "=r"(r[0]), "=r"(r[1]), "=r"(r[2]), "=r"(r[3]) : "r"(addr));
}
__device__ __forceinline__ void ldm_x4_t(unsigned* r, uint32_t addr) {
    asm volatile("ldmatrix.sync.aligned.m8n8.x4.trans.shared.b16 {%0,%1,%2,%3}, [%4];"
        : "=r"(r[0]), "=r"(r[1]), "=r"(r[2]), "=r"(r[3]) : "r"(addr));
}
__device__ __forceinline__ void mma16816(float* c, const unsigned* a, const unsigned* b) {
    asm volatile(
        "mma.sync.aligned.m16n8k16.row.col.f32.f16.f16.f32 "
        "{%0,%1,%2,%3}, {%4,%5,%6,%7}, {%8,%9}, {%0,%1,%2,%3};"
        : "+f"(c[0]), "+f"(c[1]), "+f"(c[2]), "+f"(c[3])
        : "r"(a[0]), "r"(a[1]), "r"(a[2]), "r"(a[3]), "r"(b[0]), "r"(b[1]));
}
__device__ __forceinline__ void cpa(uint32_t d, const void* s, int szvalid) {
    asm volatile("cp.async.cg.shared.global [%0], [%1], 16, %2;"
        :: "r"(d), "l"(__cvta_generic_to_global(s)), "r"(szvalid));
}

__device__ __forceinline__ void cvt8(const float* __restrict__ in, __half* __restrict__ o,
                                     size_t i)
{
    float4 a = *(const float4*)(in + i);
    float4 b = *(const float4*)(in + i + 4);
    unsigned h[4];
    h[0] = pkh(a.x, a.y); h[1] = pkh(a.z, a.w);
    h[2] = pkh(b.x, b.y); h[3] = pkh(b.z, b.w);
    *(uint4*)(o + i) = *(uint4*)h;
}

// ---------------- pipelined mma.sync fp16 GEMM (4-stage, R10 schedule) --------
// K = per-CTA loop K; lda = A row stride; ldB = B row stride.
// OP: 0 merged QKV (z=3 plane converts w1) | 1 gate split-K (raw partials, z=kh)
//     2 ow split-K (+src, z=kh) | 3 ffn1 gather +b1 | 4 ffn2 split-K (z=kh*8+e)
template <int OP>
__global__ void __launch_bounds__(256, 2) k_mm(
    const __half* __restrict__ Ah, const __half* __restrict__ B16,
    int K, int lda, int ldB,
    const float* __restrict__ bias, const float* __restrict__ extra,
    const float* __restrict__ extra2,
    __half* __restrict__ Oh, float* __restrict__ Of)
{
    if (OP == 0 && blockIdx.z == 3) {
        size_t base = (((size_t)blockIdx.y * 8 + blockIdx.x) * 256 + threadIdx.x) * 8;
        size_t stride = (size_t)128 * 256 * 8;
        for (size_t u = base; u < WELEMS; u += stride) cvt8(extra, g_w116, u);
        return;
    }

    extern __shared__ __align__(16) char sm[];
    __shared__ int rloc[TM];

    const int tid = threadIdx.x;
    const int lane = tid & 31, wid = tid >> 5;
    const int warp_m = wid >> 2, warp_n = wid & 3;
    const int row0 = blockIdx.y * TM, col0 = blockIdx.x * TN;
    int e = 0, kh = 0;
    if (OP == 0) e = blockIdx.z;
    if (OP == 1) kh = blockIdx.z;
    if (OP == 2) kh = blockIdx.z;
    if (OP == 3) e = blockIdx.z;
    if (OP == 4) { e = blockIdx.z & 7; kh = blockIdx.z >> 3; }
    int cnt = 0, off = 0;
    if (OP == 0) {
        B16 += (size_t)e * ND * ND;
        Oh += (size_t)e * NT * ND;
    }
    if (OP == 3 || OP == 4) {
        cnt = g_cnt[e]; off = g_off[e];
        if (row0 >= cnt) return;
        B16 += (size_t)e * lda * ldB;
    }
    const int koff = kh * K;
    B16 += (size_t)koff * ldB;
    if (OP == 3) {
        if (tid < TM) {
            int gr = row0 + tid;
            rloc[tid] = (gr < cnt) ? g_perm[off + gr] : -1;
        }
        __syncthreads();
    }

    const int am = tid >> 1, ahalf = tid & 1;
    int arow;
    if (OP == 3) arow = rloc[am];
    else if (OP == 4) arow = min(off + row0 + am, NT - 1);
    else arow = row0 + am;
    const int apred = (arow >= 0) ? 16 : 0;
    const int arows = (arow >= 0) ? arow : 0;
    const char* gA = (const char*)(Ah + (size_t)arows * lda + koff + ahalf * 16);
    const int bk = tid >> 3, bseg = tid & 7;
    const char* gB16 = (const char*)(B16 + (size_t)bk * ldB + col0 + bseg * 16);

    const uint32_t ub = s2u(sm);
    const uint32_t aDst = ub + ST_A + am * 80 + ahalf * 32;
    const uint32_t bDst = ub + ST_B + bk * 272 + bseg * 32;

    auto issue = [&](int stage, int c) {
        uint32_t sb = stage * STAGE_BYTES;
        size_t ao = (size_t)c * KC * 2;
        size_t bo = (size_t)c * KC * ldB * 2;
        cpa(aDst + sb,      gA + ao,      apred);
        cpa(aDst + sb + 16, gA + ao + 16, apred);
        cpa(bDst + sb,      gB16 + bo,      16);
        cpa(bDst + sb + 16, gB16 + bo + 16, 16);
        asm volatile("cp.async.commit_group;");
    };

    float acc[16][4];
#pragma unroll
    for (int t = 0; t < 16; t++)
#pragma unroll
        for (int i = 0; i < 4; i++) acc[t][i] = 0.f;

    const int nch = K / KC;
#pragma unroll
    for (int s = 0; s < NST1; s++) issue(s, s);

    for (int c = 0; c < nch; c++) {
        asm volatile("cp.async.wait_group %0;" :: "n"(NST1 - 1));
        __syncthreads();
        uint32_t sb = ub + (c % NST1) * STAGE_BYTES;
        uint32_t uA_ = sb + ST_A;
        uint32_t uB_ = sb + ST_B;
#pragma unroll
        for (int ks = 0; ks < 2; ks++) {
            unsigned b_[2][4];
#pragma unroll
            for (int nt = 0; nt < 2; nt++) {
                int krow = ks * 16 + (lane & 7) + ((lane >> 3) & 1) * 8;
                int ncol = warp_n * 32 + nt * 16 + (lane >> 4) * 8;
                uint32_t o = (uint32_t)(krow * B_STRIDE + ncol) * 2;
                ldm_x4_t(b_[nt], uB_ + o);
            }
#pragma unroll
            for (int mt = 0; mt < 4; mt++) {
                unsigned a_[4];
                int mrow = warp_m * 64 + mt * 16 + (lane & 15);
                int kcol = ks * 16 + (lane >> 4) * 8;
                uint32_t o = (uint32_t)(mrow * A_STRIDE + kcol) * 2;
                ldm_x4(a_, uA_ + o);
#pragma unroll
                for (int nt = 0; nt < 2; nt++)
#pragma unroll
                    for (int j = 0; j < 2; j++)
                        mma16816(acc[mt * 4 + nt * 2 + j], a_, b_[nt] + j * 2);
            }
        }
        __syncthreads();
        if (c + NST1 < nch) issue(c % NST1, c + NST1);
        else asm volatile("cp.async.commit_group;");
    }

    // ---- epilogue ----
    float rs = 0.f;
    if (OP == 4) rs = extra2[e];
#pragma unroll
    for (int mt = 0; mt < 4; mt++)
#pragma unroll
        for (int nt = 0; nt < 2; nt++)
#pragma unroll
            for (int j = 0; j < 2; j++) {
                float* cc = acc[mt * 4 + nt * 2 + j];
                int lcol = warp_n * 32 + nt * 16 + j * 8 + (lane & 3) * 2;
                int gcol = col0 + lcol;
#pragma unroll
                for (int half = 0; half < 2; half++) {
                    int lrow = warp_m * 64 + mt * 16 + (lane >> 2) + half * 8;
                    int gr = row0 + lrow;
                    float v0 = cc[half * 2], v1 = cc[half * 2 + 1];
                    if (OP == 0) {
                        size_t base = (size_t)gr * ND + gcol;
                        *(unsigned*)(Oh + base) = pkh(v0, v1);
                    } else if (OP == 1) {
                        size_t base = (size_t)gr * ND + gcol;
                        float2 o2; o2.x = v0; o2.y = v1;
                        *(float2*)((kh == 0 ? g_xres : g_xres2) + base) = o2;
                    } else if (OP == 2) {
                        size_t base = (size_t)gr * ND + gcol;
                        float2 o2;
                        if (kh == 0) {
                            o2.x = extra[base] + v0;
                            o2.y = extra[base + 1] + v1;
                            *(float2*)(Of + base) = o2;
                        } else {
                            o2.x = v0; o2.y = v1;
                            *(float2*)(g_xres2 + base) = o2;
                        }
                    } else if (OP == 3) {
                        if (gr < cnt) {
                            size_t base = (size_t)(off + gr) * NF + gcol;
                            float2 o2;
                            o2.x = v0 + bias[e * NF + gcol];
                            o2.y = v1 + bias[e * NF + gcol + 1];
                            *(float2*)(Of + base) = o2;
                        }
                    } else if (OP == 4) {
                        if (gr < cnt) {
                            int t = g_perm[off + gr];
                            size_t bx = (size_t)t * ND + gcol;
                            float2 o2;
                            if (kh == 0) {
                                o2.x = 2.f * extra[bx] + rs * (v0 + bias[e * ND + gcol]);
                                o2.y = 2.f * extra[bx + 1] + rs * (v1 + bias[e * ND + gcol + 1]);
                                *(float2*)(Of + bx) = o2;
                            } else {
                                o2.x = rs * v0; o2.y = rs * v1;
                                *(float2*)(g_z2 + bx) = o2;
                            }
                        }
                    }
                }
            }
}

// gate split-K fixup: g16 = fp16(a16 * sigmoid(p0 + p1 + gate_b))
__global__ __launch_bounds__(256) void k_gatefix(const float* __restrict__ gb)
{
    size_t i = ((size_t)blockIdx.x * 256 + threadIdx.x) * 4;
    float4 p0 = *(const float4*)(g_xres + i);
    float4 p1 = *(const float4*)(g_xres2 + i);
    int c = (int)(i & (ND - 1));
    __half a[4];
    *(uint2*)a = *(const uint2*)(g_a16 + i);
    float g0 = 1.f / (1.f + expf(-(p0.x + p1.x + gb[c])));
    float g1 = 1.f / (1.f + expf(-(p0.y + p1.y + gb[c + 1])));
    float g2 = 1.f / (1.f + expf(-(p0.z + p1.z + gb[c + 2])));
    float g3 = 1.f / (1.f + expf(-(p0.w + p1.w + gb[c + 3])));
    uint2 o;
    o.x = pkh(__half2float(a[0]) * g0, __half2float(a[1]) * g1);
    o.y = pkh(__half2float(a[2]) * g2, __half2float(a[3]) * g3);
    *(uint2*)(g_g16 + i) = o;
}

// ---------------- mma.sync flash attention (fused qscale) ---------------------
// z=0 plane: flash attention.  z=1 plane: stream-convert w2 fp32 -> fp16.
__global__ void __launch_bounds__(128, 4) k_flash(const float* __restrict__ w2src,
                                                  const float* __restrict__ sw)
{
    if (blockIdx.z == 1) {
        size_t cid = (size_t)blockIdx.y * 16 + blockIdx.x;  // 512 CTAs
        size_t base = (cid * 128 + threadIdx.x) * 8;
        size_t stride = (size_t)512 * 128 * 8;
        for (size_t u = base; u < WELEMS; u += stride) cvt8(w2src, g_w216, u);
        return;
    }

    extern __shared__ __align__(16) char fsm[];
    const int tid = threadIdx.x, lane = tid & 31, warpm = tid >> 5;
    const int bh = blockIdx.y, b = bh >> 4, h = bh & 15;
    const int row0 = blockIdx.x * 64;

    const __half* Qg = g_qkv;
    const __half* Kg = g_qkv + (size_t)NT * ND;
    const __half* Vg = g_qkv + (size_t)2 * NT * ND;

    // Q tile: compute per-row scale (fused qscale), apply, store fp16
    {
        int m = tid >> 1, half = tid & 1;
        const __half* src_ = Qg + (size_t)(b * NS + row0 + m) * ND + h * 64 + half * 32;
        const float* swp = sw + h * 64 + half * 32;
        uint4 raw[4];
        float part = 0.f;
#pragma unroll
        for (int i = 0; i < 4; i++) {
            raw[i] = *(const uint4*)(src_ + i * 8);
            const __half* qb = (const __half*)&raw[i];
#pragma unroll
            for (int j = 0; j < 8; j++) part += __half2float(qb[j]) * swp[i * 8 + j];
        }
        part += __shfl_xor_sync(0xffffffffu, part, 1);
        float sc = 0.25f / (1.f + expf(-part));
        char* dq = fsm + F_Q + m * 144 + half * 64;
#pragma unroll
        for (int i = 0; i < 4; i++) {
            const __half* qb = (const __half*)&raw[i];
            unsigned o4[4];
#pragma unroll
            for (int j = 0; j < 4; j++)
                o4[j] = pkh(__half2float(qb[2 * j]) * sc, __half2float(qb[2 * j + 1]) * sc);
            *(uint4*)(dq + i * 16) = *(uint4*)o4;
        }
    }

    const uint32_t ubase = s2u(fsm);
    const uint32_t uQ = ubase + F_Q, uK = ubase + F_K, uV = ubase + F_V;

    const uint32_t qa_off = ((warpm * 16 + (lane & 15)) * F_STRIDE + ((lane >> 4) & 1) * 8) * 2;
    const uint32_t ka_off = (((lane & 7) + ((lane >> 4) << 3)) * F_STRIDE + ((lane >> 3) & 1) * 8) * 2;
    const uint32_t va_off = (((lane & 7) + ((lane >> 3) & 1) * 8) * F_STRIDE + ((lane >> 4) & 1) * 8) * 2;

    float oacc[8][4];
#pragma unroll
    for (int t = 0; t < 8; t++)
#pragma unroll
        for (int i = 0; i < 4; i++) oacc[t][i] = 0.f;
    float mi0 = -1e30f, mi1 = -1e30f, li0 = 0.f, li1 = 0.f;

    for (int jt = 0; jt < NS / 64; jt++) {
        __syncthreads();
        {
            int m = tid >> 1, half = tid & 1;
            size_t gsrc = (size_t)(b * NS + jt * 64 + m) * ND + h * 64 + half * 32;
            char* dk = fsm + F_K + m * 144 + half * 64;
            char* dv = fsm + F_V + m * 144 + half * 64;
#pragma unroll
            for (int i = 0; i < 4; i++) {
                *(uint4*)(dk + i * 16) = *(const uint4*)((const char*)(Kg + gsrc) + i * 16);
                *(uint4*)(dv + i * 16) = *(const uint4*)((const char*)(Vg + gsrc) + i * 16);
            }
        }
        __syncthreads();

        float sacc[8][4];
#pragma unroll
        for (int t = 0; t < 8; t++)
#pragma unroll
            for (int i = 0; i < 4; i++) sacc[t][i] = 0.f;
#pragma unroll
        for (int ks = 0; ks < 4; ks++) {
            unsigned q4[4];
            ldm_x4(q4, uQ + qa_off + ks * 32);
#pragma unroll
            for (int np = 0; np < 4; np++) {
                unsigned k4[4];
                uint32_t o = ka_off + (uint32_t)(np * 16 * F_STRIDE + ks * 16) * 2;
                ldm_x4(k4, uK + o);
                mma16816(sacc[2 * np],     q4, k4);
                mma16816(sacc[2 * np + 1], q4, k4 + 2);
            }
        }

        float rm0 = -1e30f, rm1 = -1e30f;
#pragma unroll
        for (int j = 0; j < 8; j++) {
            rm0 = fmaxf(rm0, fmaxf(sacc[j][0], sacc[j][1]));
            rm1 = fmaxf(rm1, fmaxf(sacc[j][2], sacc[j][3]));
        }
        rm0 = fmaxf(rm0, __shfl_xor_sync(0xffffffffu, rm0, 1));
        rm0 = fmaxf(rm0, __shfl_xor_sync(0xffffffffu, rm0, 2));
        rm1 = fmaxf(rm1, __shfl_xor_sync(0xffffffffu, rm1, 1));
        rm1 = fmaxf(rm1, __shfl_xor_sync(0xffffffffu, rm1, 2));
        float mn0 = fmaxf(mi0, rm0), mn1 = fmaxf(mi1, rm1);
        float al0 = expf(mi0 - mn0), al1 = expf(mi1 - mn1);
        float rs0 = 0.f, rs1 = 0.f;
#pragma unroll
        for (int j = 0; j < 8; j++) {
            sacc[j][0] = expf(sacc[j][0] - mn0); rs0 += sacc[j][0];
            sacc[j][1] = expf(sacc[j][1] - mn0); rs0 += sacc[j][1];
            sacc[j][2] = expf(sacc[j][2] - mn1); rs1 += sacc[j][2];
            sacc[j][3] = expf(sacc[j][3] - mn1); rs1 += sacc[j][3];
        }
        rs0 += __shfl_xor_sync(0xffffffffu, rs0, 1);
        rs0 += __shfl_xor_sync(0xffffffffu, rs0, 2);
        rs1 += __shfl_xor_sync(0xffffffffu, rs1, 1);
        rs1 += __shfl_xor_sync(0xffffffffu, rs1, 2);
        li0 = li0 * al0 + rs0; li1 = li1 * al1 + rs1;
        mi0 = mn0; mi1 = mn1;
#pragma unroll
        for (int t = 0; t < 8; t++) {
            oacc[t][0] *= al0; oacc[t][1] *= al0;
            oacc[t][2] *= al1; oacc[t][3] *= al1;
        }

#pragma unroll
        for (int kb = 0; kb < 4; kb++) {
            unsigned pa[4];
            pa[0] = pkh(sacc[2 * kb][0],     sacc[2 * kb][1]);
            pa[1] = pkh(sacc[2 * kb][2],     sacc[2 * kb][3]);
            pa[2] = pkh(sacc[2 * kb + 1][0], sacc[2 * kb + 1][1]);
            pa[3] = pkh(sacc[2 * kb + 1][2], sacc[2 * kb + 1][3]);
#pragma unroll
            for (int ndp = 0; ndp < 4; ndp++) {
                unsigned v4[4];
                uint32_t o = va_off + (uint32_t)(kb * 16 * F_STRIDE + ndp * 16) * 2;
                ldm_x4_t(v4, uV + o);
                mma16816(oacc[2 * ndp],     pa, v4);
                mma16816(oacc[2 * ndp + 1], pa, v4 + 2);
            }
        }
    }

    float inv0 = 1.f / li0, inv1 = 1.f / li1;
    int r = row0 + warpm * 16 + (lane >> 2);
    int cbase = h * 64 + (lane & 3) * 2;
#pragma unroll
    for (int dt = 0; dt < 8; dt++) {
        size_t idx = (size_t)(b * NS + r) * ND + cbase + dt * 8;
        *(unsigned*)(g_a16 + idx) = pkh(oacc[dt][0] * inv0, oacc[dt][1] * inv0);
        idx += (size_t)8 * ND;
        *(unsigned*)(g_a16 + idx) = pkh(oacc[dt][2] * inv1, oacc[dt][3] * inv1);
    }
}

// ---------------- reductions --------------------------------------------------
__device__ __forceinline__ void blk_reduce2(float& s, float& q)
{
    __shared__ float ss[8], sq[8];
#pragma unroll
    for (int o = 16; o; o >>= 1) {
        s += __shfl_xor_sync(0xffffffffu, s, o);
        q += __shfl_xor_sync(0xffffffffu, q, o);
    }
    int w = threadIdx.x >> 5, l = threadIdx.x & 31;
    if (l == 0) { ss[w] = s; sq[w] = q; }
    __syncthreads();
    s = (l < 8) ? ss[l] : 0.f;
    q = (l < 8) ? sq[l] : 0.f;
#pragma unroll
    for (int o = 4; o; o >>= 1) {
        s += __shfl_xor_sync(0xffffffffu, s, o);
        q += __shfl_xor_sync(0xffffffffu, q, o);
    }
    s = __shfl_sync(0xffffffffu, s, 0);
    q = __shfl_sync(0xffffffffu, q, 0);
}

// ---------------- conversions -------------------------------------------------
__global__ __launch_bounds__(256) void k_cvt_small(
    const float* __restrict__ src, const float* __restrict__ qw,
    const float* __restrict__ kw, const float* __restrict__ vw,
    const float* __restrict__ gw, const float* __restrict__ ow)
{
    size_t u = ((size_t)blockIdx.x * 256 + threadIdx.x) * 8;
    const size_t M = (size_t)ND * ND;
    if (u < 2 * M) {
        cvt8(src, g_s16, u);
    } else if (u < 5 * M) {
        size_t v = u - 2 * M;
        if (v < M) cvt8(qw, g_wqkv, v);
        else if (v < 2 * M) cvt8(kw, g_wqkv + M, v - M);
        else cvt8(vw, g_wqkv + 2 * M, v - 2 * M);
    } else if (u < 6 * M) {
        cvt8(gw, g_wg, u - 5 * M);
    } else {
        cvt8(ow, g_wo, u - 6 * M);
    }
}

// fused LayerNorm1 + MoE routing (reads split-K partials)
__global__ __launch_bounds__(256) void k_ln1_route(
    const float* __restrict__ g, const float* __restrict__ b,
    const float* __restrict__ gw, const float* __restrict__ gb)
{
    __shared__ float slog[NE * 8];
    size_t r = blockIdx.x;
    const float* in = g_xres + r * ND;
    const float* in2 = g_xres2 + r * ND;
    float x[4];
    float s = 0.f, q = 0.f;
#pragma unroll
    for (int l = 0; l < 4; l++) {
        int c = threadIdx.x + l * 256;
        x[l] = in[c] + in2[c];
        s += x[l]; q += x[l] * x[l];
    }
    blk_reduce2(s, q);
    float mean = s * (1.f / ND);
    float var = q * (1.f / ND) - mean * mean;
    float rstd = rsqrtf(var + 1e-5f);
    float part[NE];
#pragma unroll
    for (int e = 0; e < NE; e++) part[e] = 0.f;
#pragma unroll
    for (int l = 0; l < 4; l++) {
        int c = threadIdx.x + l * 256;
        float v = (x[l] - mean) * rstd * g[c] + b[c];
        g_x[r * ND + c] = v;
        g_x16[r * ND + c] = __float2half_rn(v);
#pragma unroll
        for (int e = 0; e < NE; e++) part[e] += v * gw[c * NE + e];
    }
#pragma unroll
    for (int e = 0; e < NE; e++) {
#pragma unroll
        for (int o = 16; o; o >>= 1) part[e] += __shfl_xor_sync(0xffffffffu, part[e], o);
    }
    int w = threadIdx.x >> 5, lane = threadIdx.x & 31;
    if (lane == 0) {
#pragma unroll
        for (int e = 0; e < NE; e++) slog[w * NE + e] = part[e];
    }
    __syncthreads();
    if (threadIdx.x == 0) {
        float lg[NE];
#pragma unroll
        for (int e = 0; e < NE; e++) {
            float acc = gb[e];
#pragma unroll
            for (int w2 = 0; w2 < 8; w2++) acc += slog[w2 * NE + e];
            lg[e] = acc;
        }
        int i1 = 0; float v1 = lg[0];
#pragma unroll
        for (int e = 1; e < NE; e++) if (lg[e] > v1) { v1 = lg[e]; i1 = e; }
        int i2 = -1; float v2 = -1e30f;
#pragma unroll
        for (int e = 0; e < NE; e++) if (e != i1 && lg[e] > v2) { v2 = lg[e]; i2 = e; }
        g_esel[r] = (i1 > i2) ? i1 : i2;
    }
}

__global__ __launch_bounds__(256) void k_ln_out(const float* __restrict__ g,
                                                const float* __restrict__ b,
                                                float* __restrict__ out)
{
    size_t r = blockIdx.x;
    const float* in = g_z + r * ND;
    const float* in2 = g_z2 + r * ND;
    float x[4];
    float s = 0.f, q = 0.f;
#pragma unroll
    for (int l = 0; l < 4; l++) {
        int c = threadIdx.x + l * 256;
        x[l] = in[c] + in2[c];
        s += x[l]; q += x[l] * x[l];
    }
    blk_reduce2(s, q);
    float mean = s * (1.f / ND);
    float var = q * (1.f / ND) - mean * mean;
    float rstd = rsqrtf(var + 1e-5f);
#pragma unroll
    for (int l = 0; l < 4; l++) {
        int c = threadIdx.x + l * 256;
        out[r * ND + c] = (x[l] - mean) * rstd * g[c] + b[c];
    }
}

__global__ void k_scatter()
{
    __shared__ int scnt[NE], soff[NE], scur[NE];
    int tid = threadIdx.x;
    if (tid < NE) scnt[tid] = 0;
    __syncthreads();
    for (int t = tid; t < NT; t += 1024) atomicAdd(&scnt[g_esel[t]], 1);
    __syncthreads();
    if (tid == 0) {
        int r = 0;
        for (int e = 0; e < NE; e++) { soff[e] = r; r += scnt[e]; }
    }
    __syncthreads();
    if (tid < NE) { scur[tid] = soff[tid]; g_off[tid] = soff[tid]; g_cnt[tid] = scnt[tid]; }
    __syncthreads();
    for (int t = tid; t < NT; t += 1024) {
        int e = g_esel[t];
        int pos = atomicAdd(&scur[e], 1);
        g_perm[pos] = t;
        g_eid[pos] = e;
    }
}

__global__ __launch_bounds__(256) void k_lngelu(const float* __restrict__ lng,
                                                const float* __restrict__ lnb)
{
    int row = blockIdx.x;
    int e = g_eid[row];
    const float* hp = g_h + (size_t)row * NF;
    float x[16];
    float s = 0.f, q = 0.f;
#pragma unroll
    for (int l = 0; l < 16; l++) {
        x[l] = hp[threadIdx.x + l * 256];
        s += x[l]; q += x[l] * x[l];
    }
    blk_reduce2(s, q);
    float mean = s * (1.f / NF);
    float var = q * (1.f / NF) - mean * mean;
    float rstd = rsqrtf(var + 1e-5f);
    const float* g = lng + (size_t)e * NF;
    const float* b = lnb + (size_t)e * NF;
#pragma unroll
    for (int l = 0; l < 16; l++) {
        int c = threadIdx.x + l * 256;
        float hn = (x[l] - mean) * rstd * g[c] + b[c];
        float gel = 0.5f * hn * (1.f + erff(hn * 0.70710678118654752f));
        g_h16[(size_t)row * NF + c] = __float2half_rn(gel);
    }
}

// ---------------- launch ------------------------------------------------------
extern "C" void kernel_launch(void* const* d_in, const int* in_sizes, int n_in,
                              void* d_out, int out_size)
{
    (void)in_sizes; (void)n_in; (void)out_size;
    const float* src        = (const float*)d_in[0];
    const float* qw         = (const float*)d_in[1];
    const float* kw         = (const float*)d_in[2];
    const float* vw         = (const float*)d_in[3];
    const float* ow         = (const float*)d_in[4];
    const float* gate_w     = (const float*)d_in[5];
    const float* gate_b     = (const float*)d_in[6];
    const float* scale_w    = (const float*)d_in[7];
    const float* n1_g       = (const float*)d_in[8];
    const float* n1_b       = (const float*)d_in[9];
    const float* n2_g       = (const float*)d_in[10];
    const float* n2_b       = (const float*)d_in[11];
    const float* moe_gate_w = (const float*)d_in[12];
    const float* moe_gate_b = (const float*)d_in[13];
    const float* w1         = (const float*)d_in[14];
    const float* b1         = (const float*)d_in[15];
    const float* ln_g       = (const float*)d_in[16];
    const float* ln_b       = (const float*)d_in[17];
    const float* w2         = (const float*)d_in[18];
    const float* b2         = (const float*)d_in[19];
    const float* res_scale  = (const float*)d_in[20];
    float* out = (float*)d_out;

    cudaFuncSetAttribute((const void*)k_mm<0>, cudaFuncAttributeMaxDynamicSharedMemorySize, GEMM_SMEM);
    cudaFuncSetAttribute((const void*)k_mm<1>, cudaFuncAttributeMaxDynamicSharedMemorySize, GEMM_SMEM);
    cudaFuncSetAttribute((const void*)k_mm<2>, cudaFuncAttributeMaxDynamicSharedMemorySize, GEMM_SMEM);
    cudaFuncSetAttribute((const void*)k_mm<3>, cudaFuncAttributeMaxDynamicSharedMemorySize, GEMM_SMEM);
    cudaFuncSetAttribute((const void*)k_mm<4>, cudaFuncAttributeMaxDynamicSharedMemorySize, GEMM_SMEM);
    cudaFuncSetAttribute((const void*)k_flash, cudaFuncAttributeMaxDynamicSharedMemorySize, FLASH_SMEM);

    __half *s16, *qkv, *a16, *g16, *x16, *h16, *wqkv, *wg, *wo, *w116, *w216;
    float *xres, *x, *z, *hbuf;
    cudaGetSymbolAddress((void**)&s16, g_s16);
    cudaGetSymbolAddress((void**)&qkv, g_qkv);
    cudaGetSymbolAddress((void**)&a16, g_a16);
    cudaGetSymbolAddress((void**)&g16, g_g16);
    cudaGetSymbolAddress((void**)&x16, g_x16);
    cudaGetSymbolAddress((void**)&h16, g_h16);
    cudaGetSymbolAddress((void**)&wqkv, g_wqkv);
    cudaGetSymbolAddress((void**)&wg, g_wg);
    cudaGetSymbolAddress((void**)&wo, g_wo);
    cudaGetSymbolAddress((void**)&w116, g_w116);
    cudaGetSymbolAddress((void**)&w216, g_w216);
    cudaGetSymbolAddress((void**)&xres, g_xres);
    cudaGetSymbolAddress((void**)&x, g_x);
    cudaGetSymbolAddress((void**)&z, g_z);
    cudaGetSymbolAddress((void**)&hbuf, g_h);

    k_cvt_small<<<7 * 1024 * 1024 / 2048, 256>>>(src, qw, kw, vw, gate_w, ow);

    k_mm<0><<<dim3(ND / TN, NT / TM, 4), 256, GEMM_SMEM>>>(s16, wqkv,
        ND, ND, ND, nullptr, w1, nullptr, qkv, nullptr);
    k_flash<<<dim3(NS / 64, NB * NH, 2), 128, FLASH_SMEM>>>(w2, scale_w);
    k_mm<1><<<dim3(ND / TN, NT / TM, 2), 256, GEMM_SMEM>>>(a16, wg,
        ND / 2, ND, ND, nullptr, nullptr, nullptr, nullptr, nullptr);
    k_gatefix<<<NT * ND / 1024, 256>>>(gate_b);
    k_mm<2><<<dim3(ND / TN, NT / TM, 2), 256, GEMM_SMEM>>>(g16, wo,
        ND / 2, ND, ND, nullptr, src, nullptr, nullptr, xres);
    k_ln1_route<<<NT, 256>>>(n1_g, n1_b, moe_gate_w, moe_gate_b);
    k_scatter<<<1, 1024>>>();
    k_mm<3><<<dim3(NF / TN, NT / TM, NE), 256, GEMM_SMEM>>>(x16, w116,
        ND, ND, NF, b1, nullptr, nullptr, nullptr, hbuf);
    k_lngelu<<<NT, 256>>>(ln_g, ln_b);
    k_mm<4><<<dim3(ND / TN, NT / TM, 2 * NE), 256, GEMM_SMEM>>>(h16, w216,
        NF / 2, NF, ND, b2, x, res_scale, nullptr, z);
    k_ln_out<<<NT, 256>>>(n2_g, n2_b, out);
}

// round 15
// speedup vs baseline: 1.7312x; 1.0005x over previous
#include <cuda_runtime.h>
#include <cuda_fp16.h>
#include <math.h>
#include <stdint.h>

#define NB 2
#define NS 1024
#define ND 1024
#define NH 16
#define NE 8
#define NF 4096
#define NT 2048

#define TM 128
#define TN 128
#define KC 32
#define A_STRIDE 40    // fp16 elems per A smem row (80B)
#define B_STRIDE 136   // fp16 elems per B smem row (272B)

// 4-stage fp16 pipeline
#define ST_A 0
#define ST_B 10240
#define STAGE_BYTES 18944
#define NST1 4
#define GEMM_SMEM (NST1 * STAGE_BYTES)

#define F_STRIDE 72    // flash smem row stride (144B)
#define F_Q 0
#define F_K 9216
#define F_V 18432
#define FLASH_SMEM 27648

#define WELEMS ((size_t)NE * ND * NF)

// ---------------- scratch ----------------------------------------------------
__device__ __half g_s16[NT * ND];
__device__ __half g_qkv[3 * NT * ND];
__device__ __half g_a16[NT * ND];
__device__ __half g_g16[NT * ND];
__device__ __half g_x16[NT * ND];
__device__ __half g_h16[(size_t)NT * NF];
__device__ __half g_wqkv[3 * ND * ND];
__device__ __half g_wg[ND * ND];
__device__ __half g_wo[ND * ND];
__device__ __half g_w116[WELEMS];
__device__ __half g_w216[WELEMS];
__device__ float g_xres[NT * ND];
__device__ float g_xres2[NT * ND];
__device__ float g_x[NT * ND];
__device__ float g_z[NT * ND];
__device__ float g_z2[NT * ND];
__device__ float g_h[(size_t)NT * NF];
__device__ int g_esel[NT];
__device__ int g_perm[NT];
__device__ int g_eid[NT];
__device__ int g_off[NE];
__device__ int g_cnt[NE];

// ---------------- helpers ----------------------------------------------------
__device__ __forceinline__ uint32_t s2u(const void* p) {
    uint32_t a;
    asm("{ .reg .u64 t; cvta.to.shared.u64 t, %1; cvt.u32.u64 %0, t; }" : "=r"(a) : "l"(p));
    return a;
}
__device__ __forceinline__ unsigned pkh(float a, float b) {
    __half2 hh = __floats2half2_rn(a, b);
    return *reinterpret_cast<unsigned*>(&hh);
}
__device__ __forceinline__ void ldm_x4(unsigned* r, uint32_t addr) {
    asm volatile("ldmatrix.sync.aligned.m8n8.x4.shared.b16 {%0,%1,%2,%3}, [%4];"
        : "=r"(r[0]), "=r"(r[1]), "=r"(r[2]), "=r"(r[3]) : "r"(addr));
}
__device__ __forceinline__ void ldm_x4_t(unsigned* r, uint32_t addr) {
    asm volatile("ldmatrix.sync.aligned.m8n8.x4.trans.shared.b16 {%0,%1,%2,%3}, [%4];"
        : "=r"(r[0]), "=r"(r[1]), "=r"(r[2]), "=r"(r[3]) : "r"(addr));
}
__device__ __forceinline__ void mma16816(float* c, const unsigned* a, const unsigned* b) {
    asm volatile(
        "mma.sync.aligned.m16n8k16.row.col.f32.f16.f16.f32 "
        "{%0,%1,%2,%3}, {%4,%5,%6,%7}, {%8,%9}, {%0,%1,%2,%3};"
        : "+f"(c[0]), "+f"(c[1]), "+f"(c[2]), "+f"(c[3])
        : "r"(a[0]), "r"(a[1]), "r"(a[2]), "r"(a[3]), "r"(b[0]), "r"(b[1]));
}
__device__ __forceinline__ void cpa(uint32_t d, const void* s, int szvalid) {
    asm volatile("cp.async.cg.shared.global [%0], [%1], 16, %2;"
        :: "r"(d), "l"(__cvta_generic_to_global(s)), "r"(szvalid));
}

__device__ __forceinline__ void cvt8(const float* __restrict__ in, __half* __restrict__ o,
                                     size_t i)
{
    float4 a = *(const float4*)(in + i);
    float4 b = *(const float4*)(in + i + 4);
    unsigned h[4];
    h[0] = pkh(a.x, a.y); h[1] = pkh(a.z, a.w);
    h[2] = pkh(b.x, b.y); h[3] = pkh(b.z, b.w);
    *(uint4*)(o + i) = *(uint4*)h;
}

// ---------------- pipelined mma.sync fp16 GEMM (4-stage + frag prefetch) ------
// OP: 0 merged QKV (z=3 plane converts w1) | 1 gate split-K (raw partials, z=kh)
//     2 ow split-K (+src, z=kh) | 3 ffn1 gather +b1 | 4 ffn2 split-K (z=kh*8+e)
template <int OP>
__global__ void __launch_bounds__(256, 2) k_mm(
    const __half* __restrict__ Ah, const __half* __restrict__ B16,
    int K, int lda, int ldB,
    const float* __restrict__ bias, const float* __restrict__ extra,
    const float* __restrict__ extra2,
    __half* __restrict__ Oh, float* __restrict__ Of)
{
    if (OP == 0 && blockIdx.z == 3) {
        size_t base = (((size_t)blockIdx.y * 8 + blockIdx.x) * 256 + threadIdx.x) * 8;
        size_t stride = (size_t)128 * 256 * 8;
        for (size_t u = base; u < WELEMS; u += stride) cvt8(extra, g_w116, u);
        return;
    }

    extern __shared__ __align__(16) char sm[];
    __shared__ int rloc[TM];

    const int tid = threadIdx.x;
    const int lane = tid & 31, wid = tid >> 5;
    const int warp_m = wid >> 2, warp_n = wid & 3;
    const int row0 = blockIdx.y * TM, col0 = blockIdx.x * TN;
    int e = 0, kh = 0;
    if (OP == 0) e = blockIdx.z;
    if (OP == 1) kh = blockIdx.z;
    if (OP == 2) kh = blockIdx.z;
    if (OP == 3) e = blockIdx.z;
    if (OP == 4) { e = blockIdx.z & 7; kh = blockIdx.z >> 3; }
    int cnt = 0, off = 0;
    if (OP == 0) {
        B16 += (size_t)e * ND * ND;
        Oh += (size_t)e * NT * ND;
    }
    if (OP == 3 || OP == 4) {
        cnt = g_cnt[e]; off = g_off[e];
        if (row0 >= cnt) return;
        B16 += (size_t)e * lda * ldB;
    }
    const int koff = kh * K;
    B16 += (size_t)koff * ldB;
    if (OP == 3) {
        if (tid < TM) {
            int gr = row0 + tid;
            rloc[tid] = (gr < cnt) ? g_perm[off + gr] : -1;
        }
        __syncthreads();
    }

    const int am = tid >> 1, ahalf = tid & 1;
    int arow;
    if (OP == 3) arow = rloc[am];
    else if (OP == 4) arow = min(off + row0 + am, NT - 1);
    else arow = row0 + am;
    const int apred = (arow >= 0) ? 16 : 0;
    const int arows = (arow >= 0) ? arow : 0;
    const char* gA = (const char*)(Ah + (size_t)arows * lda + koff + ahalf * 16);
    const int bk = tid >> 3, bseg = tid & 7;
    const char* gB16 = (const char*)(B16 + (size_t)bk * ldB + col0 + bseg * 16);

    const uint32_t ub = s2u(sm);
    const uint32_t aDst = ub + ST_A + am * 80 + ahalf * 32;
    const uint32_t bDst = ub + ST_B + bk * 272 + bseg * 32;

    auto issue = [&](int stage, int c) {
        uint32_t sb = stage * STAGE_BYTES;
        size_t ao = (size_t)c * KC * 2;
        size_t bo = (size_t)c * KC * ldB * 2;
        cpa(aDst + sb,      gA + ao,      apred);
        cpa(aDst + sb + 16, gA + ao + 16, apred);
        cpa(bDst + sb,      gB16 + bo,      16);
        cpa(bDst + sb + 16, gB16 + bo + 16, 16);
        asm volatile("cp.async.commit_group;");
    };

    float acc[16][4];
#pragma unroll
    for (int t = 0; t < 16; t++)
#pragma unroll
        for (int i = 0; i < 4; i++) acc[t][i] = 0.f;

    const int nch = K / KC;
#pragma unroll
    for (int s = 0; s < NST1; s++) issue(s, s);

    const int akcol0 = (lane >> 4) * 8;
    const int amrow_base = warp_m * 64 + (lane & 15);

    for (int c = 0; c < nch; c++) {
        asm volatile("cp.async.wait_group %0;" :: "n"(NST1 - 1));
        __syncthreads();
        uint32_t sb = ub + (c % NST1) * STAGE_BYTES;
        uint32_t uA_ = sb + ST_A;
        uint32_t uB_ = sb + ST_B;
#pragma unroll
        for (int ks = 0; ks < 2; ks++) {
            unsigned b_[2][4];
#pragma unroll
            for (int nt = 0; nt < 2; nt++) {
                int krow = ks * 16 + (lane & 7) + ((lane >> 3) & 1) * 8;
                int ncol = warp_n * 32 + nt * 16 + (lane >> 4) * 8;
                uint32_t o = (uint32_t)(krow * B_STRIDE + ncol) * 2;
                ldm_x4_t(b_[nt], uB_ + o);
            }
            // fragment-level prefetch: aA/aB double buffer, compile-time alternation
            unsigned aA[4], aB[4];
            {
                uint32_t o0 = (uint32_t)((amrow_base + 0 * 16) * A_STRIDE + ks * 16 + akcol0) * 2;
                ldm_x4(aA, uA_ + o0);
            }
#pragma unroll
            for (int mt = 0; mt < 4; mt++) {
                unsigned* cur = (mt & 1) ? aB : aA;
                unsigned* nxt = (mt & 1) ? aA : aB;
                if (mt < 3) {
                    uint32_t on = (uint32_t)((amrow_base + (mt + 1) * 16) * A_STRIDE + ks * 16 + akcol0) * 2;
                    ldm_x4(nxt, uA_ + on);
                }
#pragma unroll
                for (int nt = 0; nt < 2; nt++)
#pragma unroll
                    for (int j = 0; j < 2; j++)
                        mma16816(acc[mt * 4 + nt * 2 + j], cur, b_[nt] + j * 2);
            }
        }
        __syncthreads();
        if (c + NST1 < nch) issue(c % NST1, c + NST1);
        else asm volatile("cp.async.commit_group;");
    }

    // ---- epilogue ----
    float rs = 0.f;
    if (OP == 4) rs = extra2[e];
#pragma unroll
    for (int mt = 0; mt < 4; mt++)
#pragma unroll
        for (int nt = 0; nt < 2; nt++)
#pragma unroll
            for (int j = 0; j < 2; j++) {
                float* cc = acc[mt * 4 + nt * 2 + j];
                int lcol = warp_n * 32 + nt * 16 + j * 8 + (lane & 3) * 2;
                int gcol = col0 + lcol;
#pragma unroll
                for (int half = 0; half < 2; half++) {
                    int lrow = warp_m * 64 + mt * 16 + (lane >> 2) + half * 8;
                    int gr = row0 + lrow;
                    float v0 = cc[half * 2], v1 = cc[half * 2 + 1];
                    if (OP == 0) {
                        size_t base = (size_t)gr * ND + gcol;
                        *(unsigned*)(Oh + base) = pkh(v0, v1);
                    } else if (OP == 1) {
                        size_t base = (size_t)gr * ND + gcol;
                        float2 o2; o2.x = v0; o2.y = v1;
                        *(float2*)((kh == 0 ? g_xres : g_xres2) + base) = o2;
                    } else if (OP == 2) {
                        size_t base = (size_t)gr * ND + gcol;
                        float2 o2;
                        if (kh == 0) {
                            o2.x = extra[base] + v0;
                            o2.y = extra[base + 1] + v1;
                            *(float2*)(Of + base) = o2;
                        } else {
                            o2.x = v0; o2.y = v1;
                            *(float2*)(g_xres2 + base) = o2;
                        }
                    } else if (OP == 3) {
                        if (gr < cnt) {
                            size_t base = (size_t)(off + gr) * NF + gcol;
                            float2 o2;
                            o2.x = v0 + bias[e * NF + gcol];
                            o2.y = v1 + bias[e * NF + gcol + 1];
                            *(float2*)(Of + base) = o2;
                        }
                    } else if (OP == 4) {
                        if (gr < cnt) {
                            int t = g_perm[off + gr];
                            size_t bx = (size_t)t * ND + gcol;
                            float2 o2;
                            if (kh == 0) {
                                o2.x = 2.f * extra[bx] + rs * (v0 + bias[e * ND + gcol]);
                                o2.y = 2.f * extra[bx + 1] + rs * (v1 + bias[e * ND + gcol + 1]);
                                *(float2*)(Of + bx) = o2;
                            } else {
                                o2.x = rs * v0; o2.y = rs * v1;
                                *(float2*)(g_z2 + bx) = o2;
                            }
                        }
                    }
                }
            }
}

// gate split-K fixup: g16 = fp16(a16 * sigmoid(p0 + p1 + gate_b))
__global__ __launch_bounds__(256) void k_gatefix(const float* __restrict__ gb)
{
    size_t i = ((size_t)blockIdx.x * 256 + threadIdx.x) * 4;
    float4 p0 = *(const float4*)(g_xres + i);
    float4 p1 = *(const float4*)(g_xres2 + i);
    int c = (int)(i & (ND - 1));
    __half a[4];
    *(uint2*)a = *(const uint2*)(g_a16 + i);
    float g0 = 1.f / (1.f + expf(-(p0.x + p1.x + gb[c])));
    float g1 = 1.f / (1.f + expf(-(p0.y + p1.y + gb[c + 1])));
    float g2 = 1.f / (1.f + expf(-(p0.z + p1.z + gb[c + 2])));
    float g3 = 1.f / (1.f + expf(-(p0.w + p1.w + gb[c + 3])));
    uint2 o;
    o.x = pkh(__half2float(a[0]) * g0, __half2float(a[1]) * g1);
    o.y = pkh(__half2float(a[2]) * g2, __half2float(a[3]) * g3);
    *(uint2*)(g_g16 + i) = o;
}

// ---------------- mma.sync flash attention (fused qscale + frag prefetch) -----
__global__ void __launch_bounds__(128, 4) k_flash(const float* __restrict__ w2src,
                                                  const float* __restrict__ sw)
{
    if (blockIdx.z == 1) {
        size_t cid = (size_t)blockIdx.y * 16 + blockIdx.x;
        size_t base = (cid * 128 + threadIdx.x) * 8;
        size_t stride = (size_t)512 * 128 * 8;
        for (size_t u = base; u < WELEMS; u += stride) cvt8(w2src, g_w216, u);
        return;
    }

    extern __shared__ __align__(16) char fsm[];
    const int tid = threadIdx.x, lane = tid & 31, warpm = tid >> 5;
    const int bh = blockIdx.y, b = bh >> 4, h = bh & 15;
    const int row0 = blockIdx.x * 64;

    const __half* Qg = g_qkv;
    const __half* Kg = g_qkv + (size_t)NT * ND;
    const __half* Vg = g_qkv + (size_t)2 * NT * ND;

    {
        int m = tid >> 1, half = tid & 1;
        const __half* src_ = Qg + (size_t)(b * NS + row0 + m) * ND + h * 64 + half * 32;
        const float* swp = sw + h * 64 + half * 32;
        uint4 raw[4];
        float part = 0.f;
#pragma unroll
        for (int i = 0; i < 4; i++) {
            raw[i] = *(const uint4*)(src_ + i * 8);
            const __half* qb = (const __half*)&raw[i];
#pragma unroll
            for (int j = 0; j < 8; j++) part += __half2float(qb[j]) * swp[i * 8 + j];
        }
        part += __shfl_xor_sync(0xffffffffu, part, 1);
        float sc = 0.25f / (1.f + expf(-part));
        char* dq = fsm + F_Q + m * 144 + half * 64;
#pragma unroll
        for (int i = 0; i < 4; i++) {
            const __half* qb = (const __half*)&raw[i];
            unsigned o4[4];
#pragma unroll
            for (int j = 0; j < 4; j++)
                o4[j] = pkh(__half2float(qb[2 * j]) * sc, __half2float(qb[2 * j + 1]) * sc);
            *(uint4*)(dq + i * 16) = *(uint4*)o4;
        }
    }

    const uint32_t ubase = s2u(fsm);
    const uint32_t uQ = ubase + F_Q, uK = ubase + F_K, uV = ubase + F_V;

    const uint32_t qa_off = ((warpm * 16 + (lane & 15)) * F_STRIDE + ((lane >> 4) & 1) * 8) * 2;
    const uint32_t ka_off = (((lane & 7) + ((lane >> 4) << 3)) * F_STRIDE + ((lane >> 3) & 1) * 8) * 2;
    const uint32_t va_off = (((lane & 7) + ((lane >> 3) & 1) * 8) * F_STRIDE + ((lane >> 4) & 1) * 8) * 2;

    float oacc[8][4];
#pragma unroll
    for (int t = 0; t < 8; t++)
#pragma unroll
        for (int i = 0; i < 4; i++) oacc[t][i] = 0.f;
    float mi0 = -1e30f, mi1 = -1e30f, li0 = 0.f, li1 = 0.f;

    for (int jt = 0; jt < NS / 64; jt++) {
        __syncthreads();
        {
            int m = tid >> 1, half = tid & 1;
            size_t gsrc = (size_t)(b * NS + jt * 64 + m) * ND + h * 64 + half * 32;
            char* dk = fsm + F_K + m * 144 + half * 64;
            char* dv = fsm + F_V + m * 144 + half * 64;
#pragma unroll
            for (int i = 0; i < 4; i++) {
                *(uint4*)(dk + i * 16) = *(const uint4*)((const char*)(Kg + gsrc) + i * 16);
                *(uint4*)(dv + i * 16) = *(const uint4*)((const char*)(Vg + gsrc) + i * 16);
            }
        }
        __syncthreads();

        float sacc[8][4];
#pragma unroll
        for (int t = 0; t < 8; t++)
#pragma unroll
            for (int i = 0; i < 4; i++) sacc[t][i] = 0.f;
#pragma unroll
        for (int ks = 0; ks < 4; ks++) {
            unsigned q4[4];
            ldm_x4(q4, uQ + qa_off + ks * 32);
            unsigned kA[4], kB[4];
            ldm_x4(kA, uK + ka_off + (uint32_t)(ks * 16) * 2);
#pragma unroll
            for (int np = 0; np < 4; np++) {
                unsigned* cur = (np & 1) ? kB : kA;
                unsigned* nxt = (np & 1) ? kA : kB;
                if (np < 3) {
                    uint32_t o = ka_off + (uint32_t)((np + 1) * 16 * F_STRIDE + ks * 16) * 2;
                    ldm_x4(nxt, uK + o);
                }
                mma16816(sacc[2 * np],     q4, cur);
                mma16816(sacc[2 * np + 1], q4, cur + 2);
            }
        }

        float rm0 = -1e30f, rm1 = -1e30f;
#pragma unroll
        for (int j = 0; j < 8; j++) {
            rm0 = fmaxf(rm0, fmaxf(sacc[j][0], sacc[j][1]));
            rm1 = fmaxf(rm1, fmaxf(sacc[j][2], sacc[j][3]));
        }
        rm0 = fmaxf(rm0, __shfl_xor_sync(0xffffffffu, rm0, 1));
        rm0 = fmaxf(rm0, __shfl_xor_sync(0xffffffffu, rm0, 2));
        rm1 = fmaxf(rm1, __shfl_xor_sync(0xffffffffu, rm1, 1));
        rm1 = fmaxf(rm1, __shfl_xor_sync(0xffffffffu, rm1, 2));
        float mn0 = fmaxf(mi0, rm0), mn1 = fmaxf(mi1, rm1);
        float al0 = expf(mi0 - mn0), al1 = expf(mi1 - mn1);
        float rs0 = 0.f, rs1 = 0.f;
#pragma unroll
        for (int j = 0; j < 8; j++) {
            sacc[j][0] = expf(sacc[j][0] - mn0); rs0 += sacc[j][0];
            sacc[j][1] = expf(sacc[j][1] - mn0); rs0 += sacc[j][1];
            sacc[j][2] = expf(sacc[j][2] - mn1); rs1 += sacc[j][2];
            sacc[j][3] = expf(sacc[j][3] - mn1); rs1 += sacc[j][3];
        }
        rs0 += __shfl_xor_sync(0xffffffffu, rs0, 1);
        rs0 += __shfl_xor_sync(0xffffffffu, rs0, 2);
        rs1 += __shfl_xor_sync(0xffffffffu, rs1, 1);
        rs1 += __shfl_xor_sync(0xffffffffu, rs1, 2);
        li0 = li0 * al0 + rs0; li1 = li1 * al1 + rs1;
        mi0 = mn0; mi1 = mn1;
#pragma unroll
        for (int t = 0; t < 8; t++) {
            oacc[t][0] *= al0; oacc[t][1] *= al0;
            oacc[t][2] *= al1; oacc[t][3] *= al1;
        }

#pragma unroll
        for (int kb = 0; kb < 4; kb++) {
            unsigned pa[4];
            pa[0] = pkh(sacc[2 * kb][0],     sacc[2 * kb][1]);
            pa[1] = pkh(sacc[2 * kb][2],     sacc[2 * kb][3]);
            pa[2] = pkh(sacc[2 * kb + 1][0], sacc[2 * kb + 1][1]);
            pa[3] = pkh(sacc[2 * kb + 1][2], sacc[2 * kb + 1][3]);
            unsigned vA[4], vB[4];
            ldm_x4_t(vA, uV + va_off + (uint32_t)(kb * 16 * F_STRIDE) * 2);
#pragma unroll
            for (int ndp = 0; ndp < 4; ndp++) {
                unsigned* cur = (ndp & 1) ? vB : vA;
                unsigned* nxt = (ndp & 1) ? vA : vB;
                if (ndp < 3) {
                    uint32_t o = va_off + (uint32_t)(kb * 16 * F_STRIDE + (ndp + 1) * 16) * 2;
                    ldm_x4_t(nxt, uV + o);
                }
                mma16816(oacc[2 * ndp],     pa, cur);
                mma16816(oacc[2 * ndp + 1], pa, cur + 2);
            }
        }
    }

    float inv0 = 1.f / li0, inv1 = 1.f / li1;
    int r = row0 + warpm * 16 + (lane >> 2);
    int cbase = h * 64 + (lane & 3) * 2;
#pragma unroll
    for (int dt = 0; dt < 8; dt++) {
        size_t idx = (size_t)(b * NS + r) * ND + cbase + dt * 8;
        *(unsigned*)(g_a16 + idx) = pkh(oacc[dt][0] * inv0, oacc[dt][1] * inv0);
        idx += (size_t)8 * ND;
        *(unsigned*)(g_a16 + idx) = pkh(oacc[dt][2] * inv1, oacc[dt][3] * inv1);
    }
}

// ---------------- reductions --------------------------------------------------
__device__ __forceinline__ void blk_reduce2(float& s, float& q)
{
    __shared__ float ss[8], sq[8];
#pragma unroll
    for (int o = 16; o; o >>= 1) {
        s += __shfl_xor_sync(0xffffffffu, s, o);
        q += __shfl_xor_sync(0xffffffffu, q, o);
    }
    int w = threadIdx.x >> 5, l = threadIdx.x & 31;
    if (l == 0) { ss[w] = s; sq[w] = q; }
    __syncthreads();
    s = (l < 8) ? ss[l] : 0.f;
    q = (l < 8) ? sq[l] : 0.f;
#pragma unroll
    for (int o = 4; o; o >>= 1) {
        s += __shfl_xor_sync(0xffffffffu, s, o);
        q += __shfl_xor_sync(0xffffffffu, q, o);
    }
    s = __shfl_sync(0xffffffffu, s, 0);
    q = __shfl_sync(0xffffffffu, q, 0);
}

// ---------------- conversions -------------------------------------------------
__global__ __launch_bounds__(256) void k_cvt_small(
    const float* __restrict__ src, const float* __restrict__ qw,
    const float* __restrict__ kw, const float* __restrict__ vw,
    const float* __restrict__ gw, const float* __restrict__ ow)
{
    size_t u = ((size_t)blockIdx.x * 256 + threadIdx.x) * 8;
    const size_t M = (size_t)ND * ND;
    if (u < 2 * M) {
        cvt8(src, g_s16, u);
    } else if (u < 5 * M) {
        size_t v = u - 2 * M;
        if (v < M) cvt8(qw, g_wqkv, v);
        else if (v < 2 * M) cvt8(kw, g_wqkv + M, v - M);
        else cvt8(vw, g_wqkv + 2 * M, v - 2 * M);
    } else if (u < 6 * M) {
        cvt8(gw, g_wg, u - 5 * M);
    } else {
        cvt8(ow, g_wo, u - 6 * M);
    }
}

// fused LayerNorm1 + MoE routing (reads split-K partials)
__global__ __launch_bounds__(256) void k_ln1_route(
    const float* __restrict__ g, const float* __restrict__ b,
    const float* __restrict__ gw, const float* __restrict__ gb)
{
    __shared__ float slog[NE * 8];
    size_t r = blockIdx.x;
    const float* in = g_xres + r * ND;
    const float* in2 = g_xres2 + r * ND;
    float x[4];
    float s = 0.f, q = 0.f;
#pragma unroll
    for (int l = 0; l < 4; l++) {
        int c = threadIdx.x + l * 256;
        x[l] = in[c] + in2[c];
        s += x[l]; q += x[l] * x[l];
    }
    blk_reduce2(s, q);
    float mean = s * (1.f / ND);
    float var = q * (1.f / ND) - mean * mean;
    float rstd = rsqrtf(var + 1e-5f);
    float part[NE];
#pragma unroll
    for (int e = 0; e < NE; e++) part[e] = 0.f;
#pragma unroll
    for (int l = 0; l < 4; l++) {
        int c = threadIdx.x + l * 256;
        float v = (x[l] - mean) * rstd * g[c] + b[c];
        g_x[r * ND + c] = v;
        g_x16[r * ND + c] = __float2half_rn(v);
#pragma unroll
        for (int e = 0; e < NE; e++) part[e] += v * gw[c * NE + e];
    }
#pragma unroll
    for (int e = 0; e < NE; e++) {
#pragma unroll
        for (int o = 16; o; o >>= 1) part[e] += __shfl_xor_sync(0xffffffffu, part[e], o);
    }
    int w = threadIdx.x >> 5, lane = threadIdx.x & 31;
    if (lane == 0) {
#pragma unroll
        for (int e = 0; e < NE; e++) slog[w * NE + e] = part[e];
    }
    __syncthreads();
    if (threadIdx.x == 0) {
        float lg[NE];
#pragma unroll
        for (int e = 0; e < NE; e++) {
            float acc = gb[e];
#pragma unroll
            for (int w2 = 0; w2 < 8; w2++) acc += slog[w2 * NE + e];
            lg[e] = acc;
        }
        int i1 = 0; float v1 = lg[0];
#pragma unroll
        for (int e = 1; e < NE; e++) if (lg[e] > v1) { v1 = lg[e]; i1 = e; }
        int i2 = -1; float v2 = -1e30f;
#pragma unroll
        for (int e = 0; e < NE; e++) if (e != i1 && lg[e] > v2) { v2 = lg[e]; i2 = e; }
        g_esel[r] = (i1 > i2) ? i1 : i2;
    }
}

__global__ __launch_bounds__(256) void k_ln_out(const float* __restrict__ g,
                                                const float* __restrict__ b,
                                                float* __restrict__ out)
{
    size_t r = blockIdx.x;
    const float* in = g_z + r * ND;
    const float* in2 = g_z2 + r * ND;
    float x[4];
    float s = 0.f, q = 0.f;
#pragma unroll
    for (int l = 0; l < 4; l++) {
        int c = threadIdx.x + l * 256;
        x[l] = in[c] + in2[c];
        s += x[l]; q += x[l] * x[l];
    }
    blk_reduce2(s, q);
    float mean = s * (1.f / ND);
    float var = q * (1.f / ND) - mean * mean;
    float rstd = rsqrtf(var + 1e-5f);
#pragma unroll
    for (int l = 0; l < 4; l++) {
        int c = threadIdx.x + l * 256;
        out[r * ND + c] = (x[l] - mean) * rstd * g[c] + b[c];
    }
}

__global__ void k_scatter()
{
    __shared__ int scnt[NE], soff[NE], scur[NE];
    int tid = threadIdx.x;
    if (tid < NE) scnt[tid] = 0;
    __syncthreads();
    for (int t = tid; t < NT; t += 1024) atomicAdd(&scnt[g_esel[t]], 1);
    __syncthreads();
    if (tid == 0) {
        int r = 0;
        for (int e = 0; e < NE; e++) { soff[e] = r; r += scnt[e]; }
    }
    __syncthreads();
    if (tid < NE) { scur[tid] = soff[tid]; g_off[tid] = soff[tid]; g_cnt[tid] = scnt[tid]; }
    __syncthreads();
    for (int t = tid; t < NT; t += 1024) {
        int e = g_esel[t];
        int pos = atomicAdd(&scur[e], 1);
        g_perm[pos] = t;
        g_eid[pos] = e;
    }
}

__global__ __launch_bounds__(256) void k_lngelu(const float* __restrict__ lng,
                                                const float* __restrict__ lnb)
{
    int row = blockIdx.x;
    int e = g_eid[row];
    const float* hp = g_h + (size_t)row * NF;
    float x[16];
    float s = 0.f, q = 0.f;
#pragma unroll
    for (int l = 0; l < 16; l++) {
        x[l] = hp[threadIdx.x + l * 256];
        s += x[l]; q += x[l] * x[l];
    }
    blk_reduce2(s, q);
    float mean = s * (1.f / NF);
    float var = q * (1.f / NF) - mean * mean;
    float rstd = rsqrtf(var + 1e-5f);
    const float* g = lng + (size_t)e * NF;
    const float* b = lnb + (size_t)e * NF;
#pragma unroll
    for (int l = 0; l < 16; l++) {
        int c = threadIdx.x + l * 256;
        float hn = (x[l] - mean) * rstd * g[c] + b[c];
        float gel = 0.5f * hn * (1.f + erff(hn * 0.70710678118654752f));
        g_h16[(size_t)row * NF + c] = __float2half_rn(gel);
    }
}

// ---------------- launch ------------------------------------------------------
extern "C" void kernel_launch(void* const* d_in, const int* in_sizes, int n_in,
                              void* d_out, int out_size)
{
    (void)in_sizes; (void)n_in; (void)out_size;
    const float* src        = (const float*)d_in[0];
    const float* qw         = (const float*)d_in[1];
    const float* kw         = (const float*)d_in[2];
    const float* vw         = (const float*)d_in[3];
    const float* ow         = (const float*)d_in[4];
    const float* gate_w     = (const float*)d_in[5];
    const float* gate_b     = (const float*)d_in[6];
    const float* scale_w    = (const float*)d_in[7];
    const float* n1_g       = (const float*)d_in[8];
    const float* n1_b       = (const float*)d_in[9];
    const float* n2_g       = (const float*)d_in[10];
    const float* n2_b       = (const float*)d_in[11];
    const float* moe_gate_w = (const float*)d_in[12];
    const float* moe_gate_b = (const float*)d_in[13];
    const float* w1         = (const float*)d_in[14];
    const float* b1         = (const float*)d_in[15];
    const float* ln_g       = (const float*)d_in[16];
    const float* ln_b       = (const float*)d_in[17];
    const float* w2         = (const float*)d_in[18];
    const float* b2         = (const float*)d_in[19];
    const float* res_scale  = (const float*)d_in[20];
    float* out = (float*)d_out;

    cudaFuncSetAttribute((const void*)k_mm<0>, cudaFuncAttributeMaxDynamicSharedMemorySize, GEMM_SMEM);
    cudaFuncSetAttribute((const void*)k_mm<1>, cudaFuncAttributeMaxDynamicSharedMemorySize, GEMM_SMEM);
    cudaFuncSetAttribute((const void*)k_mm<2>, cudaFuncAttributeMaxDynamicSharedMemorySize, GEMM_SMEM);
    cudaFuncSetAttribute((const void*)k_mm<3>, cudaFuncAttributeMaxDynamicSharedMemorySize, GEMM_SMEM);
    cudaFuncSetAttribute((const void*)k_mm<4>, cudaFuncAttributeMaxDynamicSharedMemorySize, GEMM_SMEM);
    cudaFuncSetAttribute((const void*)k_flash, cudaFuncAttributeMaxDynamicSharedMemorySize, FLASH_SMEM);

    __half *s16, *qkv, *a16, *g16, *x16, *h16, *wqkv, *wg, *wo, *w116, *w216;
    float *xres, *x, *z, *hbuf;
    cudaGetSymbolAddress((void**)&s16, g_s16);
    cudaGetSymbolAddress((void**)&qkv, g_qkv);
    cudaGetSymbolAddress((void**)&a16, g_a16);
    cudaGetSymbolAddress((void**)&g16, g_g16);
    cudaGetSymbolAddress((void**)&x16, g_x16);
    cudaGetSymbolAddress((void**)&h16, g_h16);
    cudaGetSymbolAddress((void**)&wqkv, g_wqkv);
    cudaGetSymbolAddress((void**)&wg, g_wg);
    cudaGetSymbolAddress((void**)&wo, g_wo);
    cudaGetSymbolAddress((void**)&w116, g_w116);
    cudaGetSymbolAddress((void**)&w216, g_w216);
    cudaGetSymbolAddress((void**)&xres, g_xres);
    cudaGetSymbolAddress((void**)&x, g_x);
    cudaGetSymbolAddress((void**)&z, g_z);
    cudaGetSymbolAddress((void**)&hbuf, g_h);

    k_cvt_small<<<7 * 1024 * 1024 / 2048, 256>>>(src, qw, kw, vw, gate_w, ow);

    k_mm<0><<<dim3(ND / TN, NT / TM, 4), 256, GEMM_SMEM>>>(s16, wqkv,
        ND, ND, ND, nullptr, w1, nullptr, qkv, nullptr);
    k_flash<<<dim3(NS / 64, NB * NH, 2), 128, FLASH_SMEM>>>(w2, scale_w);
    k_mm<1><<<dim3(ND / TN, NT / TM, 2), 256, GEMM_SMEM>>>(a16, wg,
        ND / 2, ND, ND, nullptr, nullptr, nullptr, nullptr, nullptr);
    k_gatefix<<<NT * ND / 1024, 256>>>(gate_b);
    k_mm<2><<<dim3(ND / TN, NT / TM, 2), 256, GEMM_SMEM>>>(g16, wo,
        ND / 2, ND, ND, nullptr, src, nullptr, nullptr, xres);
    k_ln1_route<<<NT, 256>>>(n1_g, n1_b, moe_gate_w, moe_gate_b);
    k_scatter<<<1, 1024>>>();
    k_mm<3><<<dim3(NF / TN, NT / TM, NE), 256, GEMM_SMEM>>>(x16, w116,
        ND, ND, NF, b1, nullptr, nullptr, nullptr, hbuf);
    k_lngelu<<<NT, 256>>>(ln_g, ln_b);
    k_mm<4><<<dim3(ND / TN, NT / TM, 2 * NE), 256, GEMM_SMEM>>>(h16, w216,
        NF / 2, NF, ND, b2, x, res_scale, nullptr, z);
    k_ln_out<<<NT, 256>>>(n2_g, n2_b, out);
}